// round 2
// baseline (speedup 1.0000x reference)
#include <cuda_runtime.h>

#define SSTEPS 16
#define NN 32768
#define EE 131072

// -------- persistent state (device globals; no allocation allowed) --------
__device__ float g_hs[(size_t)EE * 64];
__device__ float g_cs[(size_t)EE * 64];
__device__ float g_ht[(size_t)NN * 64];
__device__ float g_ct[(size_t)NN * 64];
__device__ float g_hn[(size_t)NN * 128];
__device__ float g_cn[(size_t)NN * 128];
__device__ float g_agg[(size_t)NN * 64];

__device__ __forceinline__ float sigf(float x)   { return 1.f / (1.f + __expf(-x)); }
__device__ __forceinline__ float tanh_f(float x) { return 2.f / (1.f + __expf(-2.f * x)) - 1.f; }
__device__ __forceinline__ float f4c(const float4& v, int kk) {
    return kk == 0 ? v.x : kk == 1 ? v.y : kk == 2 ? v.z : v.w;
}

// ============================================================================
// Edge LSTM (hidden 64): rows M, enc: relu(x[2] @ encw + encb) -> 64
// g = [enc, h] @ [Wih; Whh] + b   (K=128, 256 cols), LSTM update, optional
// scatter of new h into agg via inc (2 incidences per row).
// Block: 64 rows, 256 threads. Warp ty owns rows ty*8..+8; lane tx owns
// column pair tx*2 within each of the 4 gate segments (64 cols each).
// ============================================================================
__global__ __launch_bounds__(256) void edge_lstm_kernel(
    const float* __restrict__ x,
    const float* __restrict__ encw, const float* __restrict__ encb,
    const float* __restrict__ Wih,  const float* __restrict__ Whh,
    const float* __restrict__ bias,
    float* __restrict__ h, float* __restrict__ c,
    float* __restrict__ agg, const int* __restrict__ inc)
{
    __shared__ float As[64][128];   // [row][k]  k: 0..63 enc, 64..127 h
    __shared__ float Bs[16][256];   // k-chunk of combined weights

    const int tid = threadIdx.x;
    const int ty = tid >> 5, tx = tid & 31;
    const int row0 = blockIdx.x * 64;

    // ---- stage A: enc + h (coalesced global, stride-1 STS) ----
    #pragma unroll
    for (int it = 0; it < 16; ++it) {
        int idx = tid + it * 256;
        int j = idx & 63, r = idx >> 6;
        int R = row0 + r;
        float x0 = x[R * 2 + 0], x1 = x[R * 2 + 1];
        As[r][j]      = fmaxf(fmaf(x0, encw[j], fmaf(x1, encw[64 + j], encb[j])), 0.f);
        As[r][64 + j] = h[R * 64 + j];
    }

    // accumulators, initialized with bias
    float aI[8][2], aF[8][2], aG[8][2], aO[8][2];
    {
        float bi0 = bias[tx*2],       bi1 = bias[tx*2+1];
        float bf0 = bias[64 + tx*2],  bf1 = bias[64 + tx*2+1];
        float bg0 = bias[128 + tx*2], bg1 = bias[128 + tx*2+1];
        float bo0 = bias[192 + tx*2], bo1 = bias[192 + tx*2+1];
        #pragma unroll
        for (int r = 0; r < 8; ++r) {
            aI[r][0]=bi0; aI[r][1]=bi1; aF[r][0]=bf0; aF[r][1]=bf1;
            aG[r][0]=bg0; aG[r][1]=bg1; aO[r][0]=bo0; aO[r][1]=bo1;
        }
    }
    __syncthreads();

    for (int kb = 0; kb < 128; kb += 16) {
        // stage B chunk [16][256]
        #pragma unroll
        for (int it = 0; it < 4; ++it) {
            int f = tid + it * 256;
            int k = f >> 6;
            int col = (f & 63) << 2;
            int kg = kb + k;
            const float* src = (kg < 64) ? (Wih + (size_t)kg * 256 + col)
                                         : (Whh + (size_t)(kg - 64) * 256 + col);
            *(float4*)(&Bs[k][col]) = *(const float4*)src;
        }
        __syncthreads();

        #pragma unroll
        for (int k4 = 0; k4 < 4; ++k4) {
            float4 av[8];
            #pragma unroll
            for (int r = 0; r < 8; ++r)
                av[r] = *(const float4*)&As[ty * 8 + r][kb + k4 * 4];
            #pragma unroll
            for (int kk = 0; kk < 4; ++kk) {
                const int k = k4 * 4 + kk;
                float2 bI = *(const float2*)&Bs[k][tx * 2];
                float2 bF = *(const float2*)&Bs[k][64  + tx * 2];
                float2 bG = *(const float2*)&Bs[k][128 + tx * 2];
                float2 bO = *(const float2*)&Bs[k][192 + tx * 2];
                #pragma unroll
                for (int r = 0; r < 8; ++r) {
                    float a = f4c(av[r], kk);
                    aI[r][0] = fmaf(a, bI.x, aI[r][0]); aI[r][1] = fmaf(a, bI.y, aI[r][1]);
                    aF[r][0] = fmaf(a, bF.x, aF[r][0]); aF[r][1] = fmaf(a, bF.y, aF[r][1]);
                    aG[r][0] = fmaf(a, bG.x, aG[r][0]); aG[r][1] = fmaf(a, bG.y, aG[r][1]);
                    aO[r][0] = fmaf(a, bO.x, aO[r][0]); aO[r][1] = fmaf(a, bO.y, aO[r][1]);
                }
            }
        }
        __syncthreads();
    }

    // ---- LSTM epilogue (+ optional scatter into agg) ----
    #pragma unroll
    for (int r = 0; r < 8; ++r) {
        int R = row0 + ty * 8 + r;
        int j = tx * 2;
        float2 cold = *(const float2*)&c[(size_t)R * 64 + j];
        float c0 = sigf(aF[r][0]) * cold.x + sigf(aI[r][0]) * tanh_f(aG[r][0]);
        float c1 = sigf(aF[r][1]) * cold.y + sigf(aI[r][1]) * tanh_f(aG[r][1]);
        float h0 = sigf(aO[r][0]) * tanh_f(c0);
        float h1 = sigf(aO[r][1]) * tanh_f(c1);
        *(float2*)&c[(size_t)R * 64 + j] = make_float2(c0, c1);
        *(float2*)&h[(size_t)R * 64 + j] = make_float2(h0, h1);
        if (agg) {
            int n0 = inc[2 * R], n1 = inc[2 * R + 1];
            atomicAdd(&agg[(size_t)n0 * 64 + j],     h0);
            atomicAdd(&agg[(size_t)n0 * 64 + j + 1], h1);
            atomicAdd(&agg[(size_t)n1 * 64 + j],     h0);
            atomicAdd(&agg[(size_t)n1 * 64 + j + 1], h1);
        }
    }
}

// ============================================================================
// Node kernel: enc = relu(xn * nencw + nencb) (64)
//              emb = relu([ht, agg] @ eew + eeb) (64)
//              g = [enc, emb, hn] @ [Wih; Whh] + b  (K=256, 512 cols, 2 passes)
//              LSTM update (hidden 128) + out = hn @ outw + outb
// ============================================================================
#define AS_STRIDE 260
#define NODE_SMEM_FLOATS (64 * AS_STRIDE + 32 * 256)
#define NODE_SMEM_BYTES  (NODE_SMEM_FLOATS * 4)

__global__ __launch_bounds__(256) void node_kernel(
    const float* __restrict__ xn,
    const float* __restrict__ nencw, const float* __restrict__ nencb,
    const float* __restrict__ eew,   const float* __restrict__ eeb,
    const float* __restrict__ Wih,   const float* __restrict__ Whh,
    const float* __restrict__ bias,
    const float* __restrict__ outw,  const float* __restrict__ outb,
    const float* __restrict__ ht,    const float* __restrict__ agg,
    float* __restrict__ hn, float* __restrict__ cn,
    float* __restrict__ out)
{
    extern __shared__ float sm[];
    float* Asm = sm;                          // [64][AS_STRIDE]: k 0..63 enc, 64..127 emb, 128..255 (ht|agg then hn)
    float* Bsm = sm + 64 * AS_STRIDE;         // [32][256] weight chunk / eew stage (8192 floats)

    const int tid = threadIdx.x;
    const int ty = tid >> 5, tx = tid & 31;
    const int row0 = blockIdx.x * 64;

    // ---- stage enc, ht, agg ----
    #pragma unroll
    for (int it = 0; it < 16; ++it) {
        int idx = tid + it * 256;
        int j = idx & 63, r = idx >> 6;
        int R = row0 + r;
        float xv = xn[R];
        Asm[r * AS_STRIDE + j]       = fmaxf(fmaf(xv, nencw[j], nencb[j]), 0.f);
        Asm[r * AS_STRIDE + 128 + j] = ht[(size_t)R * 64 + j];
        Asm[r * AS_STRIDE + 192 + j] = agg[(size_t)R * 64 + j];
    }
    // stage eew (128x64) into Bsm flat
    #pragma unroll
    for (int it = 0; it < 8; ++it) {
        int f = tid + it * 256;
        *(float4*)&Bsm[f * 4] = *(const float4*)&eew[f * 4];
    }
    __syncthreads();

    // ---- emb GEMM: [64,128] @ [128,64], thread: one row, 16 cols ----
    {
        int r = tid >> 2, jq = tid & 3;     // r in [0,64), jq in [0,4) -> cols jq*16..+16
        float acc[16];
        #pragma unroll
        for (int g = 0; g < 4; ++g)
            #pragma unroll
            for (int u = 0; u < 4; ++u)
                acc[g * 4 + u] = eeb[jq * 16 + g * 4 + u];
        #pragma unroll 4
        for (int k = 0; k < 128; ++k) {
            float a = Asm[r * AS_STRIDE + 128 + k];
            #pragma unroll
            for (int g = 0; g < 4; ++g) {
                float4 w4 = *(const float4*)&Bsm[k * 64 + jq * 16 + g * 4];
                acc[g*4+0] = fmaf(a, w4.x, acc[g*4+0]);
                acc[g*4+1] = fmaf(a, w4.y, acc[g*4+1]);
                acc[g*4+2] = fmaf(a, w4.z, acc[g*4+2]);
                acc[g*4+3] = fmaf(a, w4.w, acc[g*4+3]);
            }
        }
        // write emb to As[.][64..127] (disjoint from the region still being read)
        #pragma unroll
        for (int g = 0; g < 4; ++g)
            #pragma unroll
            for (int u = 0; u < 4; ++u)
                Asm[r * AS_STRIDE + 64 + jq * 16 + g * 4 + u] = fmaxf(acc[g * 4 + u], 0.f);
    }
    __syncthreads();

    // ---- restage hn into As[.][128..255] ----
    #pragma unroll
    for (int it = 0; it < 32; ++it) {
        int idx = tid + it * 256;
        int j = idx & 127, r = idx >> 7;
        Asm[r * AS_STRIDE + 128 + j] = hn[(size_t)(row0 + r) * 128 + j];
    }

    // ---- main GEMM: K=256, 512 cols in 2 passes of 64 cols per gate ----
    float po[8];
    #pragma unroll
    for (int r = 0; r < 8; ++r) po[r] = 0.f;

    for (int p = 0; p < 2; ++p) {
        float aI[8][2], aF[8][2], aG[8][2], aO[8][2];
        {
            int jb = p * 64 + tx * 2;
            float bi0 = bias[jb],       bi1 = bias[jb + 1];
            float bf0 = bias[128 + jb], bf1 = bias[128 + jb + 1];
            float bg0 = bias[256 + jb], bg1 = bias[256 + jb + 1];
            float bo0 = bias[384 + jb], bo1 = bias[384 + jb + 1];
            #pragma unroll
            for (int r = 0; r < 8; ++r) {
                aI[r][0]=bi0; aI[r][1]=bi1; aF[r][0]=bf0; aF[r][1]=bf1;
                aG[r][0]=bg0; aG[r][1]=bg1; aO[r][0]=bo0; aO[r][1]=bo1;
            }
        }
        for (int kb = 0; kb < 256; kb += 32) {
            __syncthreads();
            #pragma unroll
            for (int it = 0; it < 8; ++it) {
                int f = tid + it * 256;
                int k = f >> 6;
                int lc4 = f & 63;
                int G = lc4 >> 4;
                int jj = (lc4 & 15) << 2;
                int gcol = G * 128 + p * 64 + jj;
                int kg = kb + k;
                const float* src = (kg < 128) ? (Wih + (size_t)kg * 512 + gcol)
                                              : (Whh + (size_t)(kg - 128) * 512 + gcol);
                *(float4*)&Bsm[k * 256 + (lc4 << 2)] = *(const float4*)src;
            }
            __syncthreads();
            #pragma unroll
            for (int k4 = 0; k4 < 8; ++k4) {
                float4 av[8];
                #pragma unroll
                for (int r = 0; r < 8; ++r)
                    av[r] = *(const float4*)&Asm[(ty * 8 + r) * AS_STRIDE + kb + k4 * 4];
                #pragma unroll
                for (int kk = 0; kk < 4; ++kk) {
                    const int k = k4 * 4 + kk;
                    float2 bI = *(const float2*)&Bsm[k * 256 + tx * 2];
                    float2 bF = *(const float2*)&Bsm[k * 256 + 64  + tx * 2];
                    float2 bG = *(const float2*)&Bsm[k * 256 + 128 + tx * 2];
                    float2 bO = *(const float2*)&Bsm[k * 256 + 192 + tx * 2];
                    #pragma unroll
                    for (int r = 0; r < 8; ++r) {
                        float a = f4c(av[r], kk);
                        aI[r][0] = fmaf(a, bI.x, aI[r][0]); aI[r][1] = fmaf(a, bI.y, aI[r][1]);
                        aF[r][0] = fmaf(a, bF.x, aF[r][0]); aF[r][1] = fmaf(a, bF.y, aF[r][1]);
                        aG[r][0] = fmaf(a, bG.x, aG[r][0]); aG[r][1] = fmaf(a, bG.y, aG[r][1]);
                        aO[r][0] = fmaf(a, bO.x, aO[r][0]); aO[r][1] = fmaf(a, bO.y, aO[r][1]);
                    }
                }
            }
        }

        // epilogue for this pass's 64 hidden cells
        #pragma unroll
        for (int r = 0; r < 8; ++r) {
            int R = row0 + ty * 8 + r;
            int j = p * 64 + tx * 2;
            float2 cold = *(const float2*)&cn[(size_t)R * 128 + j];
            float c0 = sigf(aF[r][0]) * cold.x + sigf(aI[r][0]) * tanh_f(aG[r][0]);
            float c1 = sigf(aF[r][1]) * cold.y + sigf(aI[r][1]) * tanh_f(aG[r][1]);
            float h0 = sigf(aO[r][0]) * tanh_f(c0);
            float h1 = sigf(aO[r][1]) * tanh_f(c1);
            *(float2*)&cn[(size_t)R * 128 + j] = make_float2(c0, c1);
            *(float2*)&hn[(size_t)R * 128 + j] = make_float2(h0, h1);
            po[r] = fmaf(h0, outw[j],     po[r]);
            po[r] = fmaf(h1, outw[j + 1], po[r]);
        }
    }

    // out = hn @ outw + outb : reduce po across the warp
    #pragma unroll
    for (int off = 16; off; off >>= 1)
        #pragma unroll
        for (int r = 0; r < 8; ++r)
            po[r] += __shfl_xor_sync(0xffffffffu, po[r], off);
    if (tx == 0) {
        float ob = outb[0];
        #pragma unroll
        for (int r = 0; r < 8; ++r)
            out[row0 + ty * 8 + r] = po[r] + ob;
    }
}

// ============================================================================
extern "C" void kernel_launch(void* const* d_in, const int* in_sizes, int n_in,
                              void* d_out, int out_size) {
    const float* data_nodes = (const float*)d_in[0];
    const float* data_te    = (const float*)d_in[1];
    const float* data_se    = (const float*)d_in[2];
    const float* h_n0 = (const float*)d_in[3];
    const float* c_n0 = (const float*)d_in[4];
    const float* h_t0 = (const float*)d_in[5];
    const float* c_t0 = (const float*)d_in[6];
    const float* h_s0 = (const float*)d_in[7];
    const float* c_s0 = (const float*)d_in[8];
    const int*   inc  = (const int*)d_in[9];
    const float* t_enc_w = (const float*)d_in[10];
    const float* t_enc_b = (const float*)d_in[11];
    const float* t_Wih   = (const float*)d_in[12];
    const float* t_Whh   = (const float*)d_in[13];
    const float* t_b     = (const float*)d_in[14];
    const float* s_enc_w = (const float*)d_in[15];
    const float* s_enc_b = (const float*)d_in[16];
    const float* s_Wih   = (const float*)d_in[17];
    const float* s_Whh   = (const float*)d_in[18];
    const float* s_b     = (const float*)d_in[19];
    const float* n_enc_w = (const float*)d_in[20];
    const float* n_enc_b = (const float*)d_in[21];
    const float* ee_w    = (const float*)d_in[22];
    const float* ee_b    = (const float*)d_in[23];
    const float* n_Wih   = (const float*)d_in[24];
    const float* n_Whh   = (const float*)d_in[25];
    const float* n_b     = (const float*)d_in[26];
    const float* out_w   = (const float*)d_in[27];
    const float* out_b   = (const float*)d_in[28];
    float* out = (float*)d_out;

    float *hs, *cs, *ht, *ct, *hn, *cn, *agg;
    cudaGetSymbolAddress((void**)&hs,  g_hs);
    cudaGetSymbolAddress((void**)&cs,  g_cs);
    cudaGetSymbolAddress((void**)&ht,  g_ht);
    cudaGetSymbolAddress((void**)&ct,  g_ct);
    cudaGetSymbolAddress((void**)&hn,  g_hn);
    cudaGetSymbolAddress((void**)&cn,  g_cn);
    cudaGetSymbolAddress((void**)&agg, g_agg);

    cudaMemcpyAsync(hs, h_s0, (size_t)EE * 64  * 4, cudaMemcpyDeviceToDevice);
    cudaMemcpyAsync(cs, c_s0, (size_t)EE * 64  * 4, cudaMemcpyDeviceToDevice);
    cudaMemcpyAsync(ht, h_t0, (size_t)NN * 64  * 4, cudaMemcpyDeviceToDevice);
    cudaMemcpyAsync(ct, c_t0, (size_t)NN * 64  * 4, cudaMemcpyDeviceToDevice);
    cudaMemcpyAsync(hn, h_n0, (size_t)NN * 128 * 4, cudaMemcpyDeviceToDevice);
    cudaMemcpyAsync(cn, c_n0, (size_t)NN * 128 * 4, cudaMemcpyDeviceToDevice);

    cudaFuncSetAttribute(node_kernel, cudaFuncAttributeMaxDynamicSharedMemorySize,
                         NODE_SMEM_BYTES);

    for (int t = 0; t < SSTEPS; ++t) {
        cudaMemsetAsync(agg, 0, (size_t)NN * 64 * 4);
        edge_lstm_kernel<<<EE / 64, 256>>>(data_se + (size_t)t * EE * 2,
                                           s_enc_w, s_enc_b, s_Wih, s_Whh, s_b,
                                           hs, cs, agg, inc);
        edge_lstm_kernel<<<NN / 64, 256>>>(data_te + (size_t)t * NN * 2,
                                           t_enc_w, t_enc_b, t_Wih, t_Whh, t_b,
                                           ht, ct, nullptr, nullptr);
        node_kernel<<<NN / 64, 256, NODE_SMEM_BYTES>>>(
            data_nodes + (size_t)t * NN,
            n_enc_w, n_enc_b, ee_w, ee_b, n_Wih, n_Whh, n_b, out_w, out_b,
            ht, agg, hn, cn, out + (size_t)t * NN);
    }
}

// round 3
// speedup vs baseline: 1.1287x; 1.1287x over previous
#include <cuda_runtime.h>
#include <cuda_bf16.h>
#include <cstdint>

#define SSTEPS 16
#define NN 32768
#define EE 131072

// -------- persistent state (device globals; no allocation allowed) --------
__device__ float g_hs[(size_t)EE * 64];
__device__ float g_cs[(size_t)EE * 64];
__device__ float g_ht[(size_t)NN * 64];
__device__ float g_ct[(size_t)NN * 64];
__device__ float g_hn[(size_t)NN * 128];
__device__ float g_cn[(size_t)NN * 128];
__device__ float g_agg[(size_t)NN * 64];

// pre-split n-major weights (bf16 hi|lo along k)
__device__ __nv_bfloat16 g_w2t_s[256 * 256];   // [n=256][k'=256] (hi:0..127, lo:128..255)
__device__ __nv_bfloat16 g_w2t_t[256 * 256];
__device__ __nv_bfloat16 g_w2t_n[512 * 512];   // [n=512][k'=512] (hi:0..255, lo:256..511)

__device__ __forceinline__ float sigf(float x)   { return 1.f / (1.f + __expf(-x)); }
__device__ __forceinline__ float tanh_f(float x) { return 2.f / (1.f + __expf(-2.f * x)) - 1.f; }

__device__ __forceinline__ uint32_t smem_u32(const void* p) {
    return (uint32_t)__cvta_generic_to_shared(p);
}

#define LDSM4(r0, r1, r2, r3, addr) \
    asm volatile("ldmatrix.sync.aligned.m8n8.x4.shared.b16 {%0,%1,%2,%3},[%4];" \
                 : "=r"(r0), "=r"(r1), "=r"(r2), "=r"(r3) : "r"(addr))

#define MMA_BF16(D, a0, a1, a2, a3, b0, b1) \
    asm volatile("mma.sync.aligned.m16n8k16.row.col.f32.bf16.bf16.f32 " \
                 "{%0,%1,%2,%3},{%4,%5,%6,%7},{%8,%9},{%0,%1,%2,%3};" \
                 : "+f"(D[0]), "+f"(D[1]), "+f"(D[2]), "+f"(D[3]) \
                 : "r"(a0), "r"(a1), "r"(a2), "r"(a3), "r"(b0), "r"(b1))

#define CP16(saddr, gptr) \
    asm volatile("cp.async.ca.shared.global [%0],[%1],16;" :: "r"(saddr), "l"(gptr))
#define CP_COMMIT() asm volatile("cp.async.commit_group;")
#define CP_WAIT0()  asm volatile("cp.async.wait_group 0;")

__device__ __forceinline__ void split_bf16(float v, __nv_bfloat16& hi, __nv_bfloat16& lo) {
    hi = __float2bfloat16(v);
    lo = __float2bfloat16(v - __bfloat162float(hi));
}

// ============================================================================
// weight prep kernels (run once per launch)
// ============================================================================
__global__ void prep_edge_w(const float* __restrict__ Wih, const float* __restrict__ Whh,
                            __nv_bfloat16* __restrict__ W2t) {
    int idx = blockIdx.x * 256 + threadIdx.x;      // 256 n * 128 k
    int n = idx >> 7, k = idx & 127;
    float v = (k < 64) ? Wih[k * 256 + n] : Whh[(k - 64) * 256 + n];
    __nv_bfloat16 hi, lo; split_bf16(v, hi, lo);
    W2t[n * 256 + k] = hi;
    W2t[n * 256 + 128 + k] = lo;
}

__global__ void prep_node_w(const float* __restrict__ Wih, const float* __restrict__ Whh,
                            __nv_bfloat16* __restrict__ W2t) {
    int idx = blockIdx.x * 256 + threadIdx.x;      // 512 n * 256 k
    int n = idx >> 8, k = idx & 255;
    float v = (k < 128) ? Wih[k * 512 + n] : Whh[(k - 128) * 512 + n];
    __nv_bfloat16 hi, lo; split_bf16(v, hi, lo);
    W2t[n * 512 + k] = hi;
    W2t[n * 512 + 256 + k] = lo;
}

// ============================================================================
// Edge LSTM (hidden 64, K=128, N=256) via 3-pass bf16 mma
// Block: 64 rows, 8 warps (4 along M x 2 along N). Warp tile m16 x n128.
// ============================================================================
#define E_AS_STRIDE 136                         // bf16 elems (128 + 8 pad)
#define E_AS_BYTES  (64 * E_AS_STRIDE * 2)      // 17408
#define E_BS_STRIDE 24                          // bf16 elems (16 + 8 pad)
#define E_BS_BYTES  (256 * E_BS_STRIDE * 2)     // 12288 per buffer
#define EDGE_SMEM   (2 * E_AS_BYTES + 2 * E_BS_BYTES)   // 59392

__global__ __launch_bounds__(256) void edge_mma_kernel(
    const float* __restrict__ x,
    const float* __restrict__ encw, const float* __restrict__ encb,
    const __nv_bfloat16* __restrict__ W2t,
    const float* __restrict__ bias,
    float* __restrict__ h, float* __restrict__ c,
    float* __restrict__ agg, const int* __restrict__ inc)
{
    extern __shared__ char sm_raw[];
    __nv_bfloat16* As_hi = (__nv_bfloat16*)sm_raw;                       // [64][136]
    __nv_bfloat16* As_lo = (__nv_bfloat16*)(sm_raw + E_AS_BYTES);
    __nv_bfloat16* Bs    = (__nv_bfloat16*)(sm_raw + 2 * E_AS_BYTES);    // [2][256][24]

    const int tid = threadIdx.x;
    const int wid = tid >> 5, l = tid & 31;
    const int mw = wid & 3, nw = wid >> 2;
    const int m0 = mw * 16;
    const int row0 = blockIdx.x * 64;

    // ---- stage A (enc + h), split to hi/lo planes ----
    #pragma unroll
    for (int it = 0; it < 16; ++it) {
        int idx = tid + it * 256;
        int j = idx & 63, r = idx >> 6;
        int R = row0 + r;
        float x0 = x[R * 2 + 0], x1 = x[R * 2 + 1];
        float ve = fmaxf(fmaf(x0, encw[j], fmaf(x1, encw[64 + j], encb[j])), 0.f);
        __nv_bfloat16 hi, lo;
        split_bf16(ve, hi, lo);
        As_hi[r * E_AS_STRIDE + j] = hi; As_lo[r * E_AS_STRIDE + j] = lo;
        float vh = h[(size_t)R * 64 + j];
        split_bf16(vh, hi, lo);
        As_hi[r * E_AS_STRIDE + 64 + j] = hi; As_lo[r * E_AS_STRIDE + 64 + j] = lo;
    }

    // lane-constant ldmatrix offsets (bytes)
    const uint32_t hiBase = smem_u32(As_hi), loBase = smem_u32(As_lo), bBase = smem_u32(Bs);
    const uint32_t a_off = ((m0 + (l & 15)) * E_AS_STRIDE + ((l >> 4) << 3)) * 2;
    const int qi = l >> 3, ii = l & 7;
    uint32_t boff[4][2];
    #pragma unroll
    for (int jt = 0; jt < 4; ++jt)
        #pragma unroll
        for (int pr = 0; pr < 2; ++pr) {
            int gA = pr * 2, gB = gA + 1;
            int n0A = gA * 64 + nw * 32 + jt * 8;
            int n0B = gB * 64 + nw * 32 + jt * 8;
            int row = ((qi < 2) ? n0A : n0B) + ii;
            int kc = (qi & 1) * 8;
            boff[jt][pr] = (row * E_BS_STRIDE + kc) * 2;
        }

    float acc[4][4][4];
    #pragma unroll
    for (int jt = 0; jt < 4; ++jt)
        #pragma unroll
        for (int g = 0; g < 4; ++g)
            #pragma unroll
            for (int e = 0; e < 4; ++e) acc[jt][g][e] = 0.f;

    // ---- stage first B chunk ----
    {
        int koff = 0;   // chunk 0: hi block, cc=0
        const __nv_bfloat16* src = W2t + tid * 256 + koff;
        uint32_t dst = bBase + (tid * E_BS_STRIDE) * 2;
        CP16(dst, src); CP16(dst + 16, src + 8);
        CP_COMMIT();
    }

    // ---- 24 k-chunks: blocks {Ahi*Bhi, Alo*Bhi, Ahi*Blo} x 8 ----
    for (int cg = 0; cg < 24; ++cg) {
        CP_WAIT0();
        __syncthreads();
        if (cg < 23) {
            int cn2 = cg + 1;
            int b2 = cn2 >> 3, cc2 = cn2 & 7;
            int koff = ((b2 == 2) ? 128 : 0) + cc2 * 16;
            const __nv_bfloat16* src = W2t + tid * 256 + koff;
            uint32_t dst = bBase + (((cn2 & 1) * 256 + tid) * E_BS_STRIDE) * 2;
            CP16(dst, src); CP16(dst + 16, src + 8);
            CP_COMMIT();
        }
        int b = cg >> 3, kk0 = (cg & 7) * 16;
        uint32_t abase = ((b == 1) ? loBase : hiBase) + a_off + kk0 * 2;
        uint32_t a0, a1, a2, a3;
        LDSM4(a0, a1, a2, a3, abase);

        uint32_t bufo = (cg & 1) * E_BS_BYTES;
        uint32_t bb[4][4][2];
        #pragma unroll
        for (int jt = 0; jt < 4; ++jt)
            #pragma unroll
            for (int pr = 0; pr < 2; ++pr) {
                uint32_t r0, r1, r2, r3;
                LDSM4(r0, r1, r2, r3, bBase + bufo + boff[jt][pr]);
                bb[jt][pr * 2][0] = r0;     bb[jt][pr * 2][1] = r1;
                bb[jt][pr * 2 + 1][0] = r2; bb[jt][pr * 2 + 1][1] = r3;
            }
        #pragma unroll
        for (int jt = 0; jt < 4; ++jt)
            #pragma unroll
            for (int g = 0; g < 4; ++g)
                MMA_BF16(acc[jt][g], a0, a1, a2, a3, bb[jt][g][0], bb[jt][g][1]);
    }

    // ---- LSTM epilogue (+ optional scatter) ----
    const int r_in = l >> 2, cbase = 2 * (l & 3);
    #pragma unroll
    for (int jt = 0; jt < 4; ++jt) {
        int j0 = nw * 32 + jt * 8 + cbase;
        #pragma unroll
        for (int p = 0; p < 2; ++p) {
            int R = row0 + m0 + r_in + 8 * p;
            float i0 = acc[jt][0][p * 2]     + bias[j0];
            float i1 = acc[jt][0][p * 2 + 1] + bias[j0 + 1];
            float f0 = acc[jt][1][p * 2]     + bias[64 + j0];
            float f1 = acc[jt][1][p * 2 + 1] + bias[64 + j0 + 1];
            float gg0 = acc[jt][2][p * 2]     + bias[128 + j0];
            float gg1 = acc[jt][2][p * 2 + 1] + bias[128 + j0 + 1];
            float o0 = acc[jt][3][p * 2]     + bias[192 + j0];
            float o1 = acc[jt][3][p * 2 + 1] + bias[192 + j0 + 1];
            float2 cold = *(const float2*)&c[(size_t)R * 64 + j0];
            float c0 = sigf(f0) * cold.x + sigf(i0) * tanh_f(gg0);
            float c1 = sigf(f1) * cold.y + sigf(i1) * tanh_f(gg1);
            float h0 = sigf(o0) * tanh_f(c0);
            float h1 = sigf(o1) * tanh_f(c1);
            *(float2*)&c[(size_t)R * 64 + j0] = make_float2(c0, c1);
            *(float2*)&h[(size_t)R * 64 + j0] = make_float2(h0, h1);
            if (agg) {
                int n0 = inc[2 * R], n1 = inc[2 * R + 1];
                atomicAdd(&agg[(size_t)n0 * 64 + j0],     h0);
                atomicAdd(&agg[(size_t)n0 * 64 + j0 + 1], h1);
                atomicAdd(&agg[(size_t)n1 * 64 + j0],     h0);
                atomicAdd(&agg[(size_t)n1 * 64 + j0 + 1], h1);
            }
        }
    }
}

// ============================================================================
// Node kernel (hidden 128, K=256, N=512; 2 passes of 256 staged cols)
// ============================================================================
#define N_AS_STRIDE 264                          // bf16 elems (256 + 8 pad)
#define N_AS_BYTES  (64 * N_AS_STRIDE * 2)       // 33792
#define N_ASF_BYTES (64 * 132 * 4)               // 33792 fp32 [ht|agg]
#define N_EEW_BYTES (128 * 64 * 4)               // 32768
#define N_BS_BYTES  (256 * E_BS_STRIDE * 2)      // 12288 per buffer
#define NODE_SMEM   (2 * N_AS_BYTES + N_ASF_BYTES + N_EEW_BYTES + 2 * N_BS_BYTES + 256)

__global__ __launch_bounds__(256) void node_mma_kernel(
    const float* __restrict__ xn,
    const float* __restrict__ nencw, const float* __restrict__ nencb,
    const float* __restrict__ eew,   const float* __restrict__ eeb,
    const __nv_bfloat16* __restrict__ W2t,
    const float* __restrict__ bias,
    const float* __restrict__ outw,  const float* __restrict__ outb,
    const float* __restrict__ ht,    const float* __restrict__ agg,
    float* __restrict__ hn, float* __restrict__ cn,
    float* __restrict__ out)
{
    extern __shared__ char sm_raw[];
    __nv_bfloat16* As_hi = (__nv_bfloat16*)sm_raw;                              // [64][264]
    __nv_bfloat16* As_lo = (__nv_bfloat16*)(sm_raw + N_AS_BYTES);
    float* As_f  = (float*)(sm_raw + 2 * N_AS_BYTES);                           // [64][132]
    float* eew_s = (float*)(sm_raw + 2 * N_AS_BYTES + N_ASF_BYTES);             // [128][64]
    __nv_bfloat16* Bs = (__nv_bfloat16*)(sm_raw + 2 * N_AS_BYTES + N_ASF_BYTES + N_EEW_BYTES);
    float* out_s = (float*)(sm_raw + 2 * N_AS_BYTES + N_ASF_BYTES + N_EEW_BYTES + 2 * N_BS_BYTES);

    const int tid = threadIdx.x;
    const int wid = tid >> 5, l = tid & 31;
    const int mw = wid & 3, nw = wid >> 2;
    const int m0 = mw * 16;
    const int row0 = blockIdx.x * 64;

    if (tid < 64) out_s[tid] = 0.f;

    // ---- stage: enc (bf16 planes, cols 0..63), ht|agg (fp32), hn (bf16 128..255), eew ----
    #pragma unroll
    for (int it = 0; it < 16; ++it) {
        int idx = tid + it * 256;
        int j = idx & 63, r = idx >> 6;
        int R = row0 + r;
        float xv = xn[R];
        float ve = fmaxf(fmaf(xv, nencw[j], nencb[j]), 0.f);
        __nv_bfloat16 hi, lo;
        split_bf16(ve, hi, lo);
        As_hi[r * N_AS_STRIDE + j] = hi; As_lo[r * N_AS_STRIDE + j] = lo;
        As_f[r * 132 + j]      = ht[(size_t)R * 64 + j];
        As_f[r * 132 + 64 + j] = agg[(size_t)R * 64 + j];
    }
    #pragma unroll
    for (int it = 0; it < 32; ++it) {
        int idx = tid + it * 256;
        int j = idx & 127, r = idx >> 7;
        float vh = hn[(size_t)(row0 + r) * 128 + j];
        __nv_bfloat16 hi, lo;
        split_bf16(vh, hi, lo);
        As_hi[r * N_AS_STRIDE + 128 + j] = hi; As_lo[r * N_AS_STRIDE + 128 + j] = lo;
    }
    #pragma unroll
    for (int it = 0; it < 8; ++it) {
        int f4 = tid + it * 256;
        *(float4*)&eew_s[f4 * 4] = *(const float4*)&eew[f4 * 4];
    }
    __syncthreads();

    // ---- emb GEMM fp32: [64,128] @ [128,64] -> relu -> bf16 planes cols 64..127 ----
    {
        int r = tid >> 2, jq = tid & 3;
        float accv[16];
        #pragma unroll
        for (int g = 0; g < 4; ++g)
            #pragma unroll
            for (int u = 0; u < 4; ++u)
                accv[g * 4 + u] = eeb[jq * 16 + g * 4 + u];
        #pragma unroll 4
        for (int k = 0; k < 128; ++k) {
            float a = As_f[r * 132 + k];
            #pragma unroll
            for (int g = 0; g < 4; ++g) {
                float4 w4 = *(const float4*)&eew_s[k * 64 + jq * 16 + g * 4];
                accv[g*4+0] = fmaf(a, w4.x, accv[g*4+0]);
                accv[g*4+1] = fmaf(a, w4.y, accv[g*4+1]);
                accv[g*4+2] = fmaf(a, w4.z, accv[g*4+2]);
                accv[g*4+3] = fmaf(a, w4.w, accv[g*4+3]);
            }
        }
        #pragma unroll
        for (int g = 0; g < 4; ++g)
            #pragma unroll
            for (int u = 0; u < 4; ++u) {
                float v = fmaxf(accv[g * 4 + u], 0.f);
                __nv_bfloat16 hi, lo;
                split_bf16(v, hi, lo);
                int col = 64 + jq * 16 + g * 4 + u;
                As_hi[r * N_AS_STRIDE + col] = hi;
                As_lo[r * N_AS_STRIDE + col] = lo;
            }
    }

    // lane-constant ldmatrix offsets
    const uint32_t hiBase = smem_u32(As_hi), loBase = smem_u32(As_lo), bBase = smem_u32(Bs);
    const uint32_t a_off = ((m0 + (l & 15)) * N_AS_STRIDE + ((l >> 4) << 3)) * 2;
    const int qi = l >> 3, ii = l & 7;
    uint32_t boff[4][2];
    #pragma unroll
    for (int jt = 0; jt < 4; ++jt)
        #pragma unroll
        for (int pr = 0; pr < 2; ++pr) {
            int gA = pr * 2, gB = gA + 1;
            int n0A = gA * 64 + nw * 32 + jt * 8;
            int n0B = gB * 64 + nw * 32 + jt * 8;
            int row = ((qi < 2) ? n0A : n0B) + ii;
            int kc = (qi & 1) * 8;
            boff[jt][pr] = (row * E_BS_STRIDE + kc) * 2;
        }

    // staged-row -> global n (pass-dependent)
    const int sg = tid >> 6, sj = tid & 63;   // staged col s=tid: gate, j

    const int r_in = l >> 2, cbase = 2 * (l & 3);
    float po0 = 0.f, po1 = 0.f;

    for (int p = 0; p < 2; ++p) {
        __syncthreads();   // prior pass's Bs reads done before restaging buf0

        float acc[4][4][4];
        #pragma unroll
        for (int jt = 0; jt < 4; ++jt)
            #pragma unroll
            for (int g = 0; g < 4; ++g)
                #pragma unroll
                for (int e = 0; e < 4; ++e) acc[jt][g][e] = 0.f;

        const int ng = sg * 128 + p * 64 + sj;          // global weight row for this thread
        {
            const __nv_bfloat16* src = W2t + (size_t)ng * 512;   // chunk 0: hi, koff 0
            uint32_t dst = bBase + (tid * E_BS_STRIDE) * 2;
            CP16(dst, src); CP16(dst + 16, src + 8);
            CP_COMMIT();
        }

        for (int cg = 0; cg < 48; ++cg) {
            CP_WAIT0();
            __syncthreads();
            if (cg < 47) {
                int cn2 = cg + 1;
                int b2 = cn2 >> 4, cc2 = cn2 & 15;
                int koff = ((b2 == 2) ? 256 : 0) + cc2 * 16;
                const __nv_bfloat16* src = W2t + (size_t)ng * 512 + koff;
                uint32_t dst = bBase + (((cn2 & 1) * 256 + tid) * E_BS_STRIDE) * 2;
                CP16(dst, src); CP16(dst + 16, src + 8);
                CP_COMMIT();
            }
            int b = cg >> 4, kk0 = (cg & 15) * 16;
            uint32_t abase = ((b == 1) ? loBase : hiBase) + a_off + kk0 * 2;
            uint32_t a0, a1, a2, a3;
            LDSM4(a0, a1, a2, a3, abase);

            uint32_t bufo = (cg & 1) * N_BS_BYTES;
            uint32_t bb[4][4][2];
            #pragma unroll
            for (int jt = 0; jt < 4; ++jt)
                #pragma unroll
                for (int pr = 0; pr < 2; ++pr) {
                    uint32_t r0, r1, r2, r3;
                    LDSM4(r0, r1, r2, r3, bBase + bufo + boff[jt][pr]);
                    bb[jt][pr * 2][0] = r0;     bb[jt][pr * 2][1] = r1;
                    bb[jt][pr * 2 + 1][0] = r2; bb[jt][pr * 2 + 1][1] = r3;
                }
            #pragma unroll
            for (int jt = 0; jt < 4; ++jt)
                #pragma unroll
                for (int g = 0; g < 4; ++g)
                    MMA_BF16(acc[jt][g], a0, a1, a2, a3, bb[jt][g][0], bb[jt][g][1]);
        }

        // ---- epilogue for this pass's 64 hidden cells ----
        #pragma unroll
        for (int jt = 0; jt < 4; ++jt) {
            int j0 = nw * 32 + jt * 8 + cbase;
            int jh = p * 64 + j0;
            #pragma unroll
            for (int pp = 0; pp < 2; ++pp) {
                int R = row0 + m0 + r_in + 8 * pp;
                float i0 = acc[jt][0][pp * 2]     + bias[jh];
                float i1 = acc[jt][0][pp * 2 + 1] + bias[jh + 1];
                float f0 = acc[jt][1][pp * 2]     + bias[128 + jh];
                float f1 = acc[jt][1][pp * 2 + 1] + bias[128 + jh + 1];
                float gg0 = acc[jt][2][pp * 2]     + bias[256 + jh];
                float gg1 = acc[jt][2][pp * 2 + 1] + bias[256 + jh + 1];
                float o0 = acc[jt][3][pp * 2]     + bias[384 + jh];
                float o1 = acc[jt][3][pp * 2 + 1] + bias[384 + jh + 1];
                float2 cold = *(const float2*)&cn[(size_t)R * 128 + jh];
                float c0 = sigf(f0) * cold.x + sigf(i0) * tanh_f(gg0);
                float c1 = sigf(f1) * cold.y + sigf(i1) * tanh_f(gg1);
                float h0 = sigf(o0) * tanh_f(c0);
                float h1 = sigf(o1) * tanh_f(c1);
                *(float2*)&cn[(size_t)R * 128 + jh] = make_float2(c0, c1);
                *(float2*)&hn[(size_t)R * 128 + jh] = make_float2(h0, h1);
                float contrib = fmaf(h0, outw[jh], h1 * outw[jh + 1]);
                if (pp == 0) po0 += contrib; else po1 += contrib;
            }
        }
    }

    // ---- out = hn @ outw + outb ----
    #pragma unroll
    for (int off = 1; off <= 2; off <<= 1) {
        po0 += __shfl_xor_sync(0xffffffffu, po0, off);
        po1 += __shfl_xor_sync(0xffffffffu, po1, off);
    }
    if ((l & 3) == 0) {
        atomicAdd(&out_s[m0 + r_in],     po0);
        atomicAdd(&out_s[m0 + r_in + 8], po1);
    }
    __syncthreads();
    if (tid < 64) out[row0 + tid] = out_s[tid] + outb[0];
}

// ============================================================================
extern "C" void kernel_launch(void* const* d_in, const int* in_sizes, int n_in,
                              void* d_out, int out_size) {
    const float* data_nodes = (const float*)d_in[0];
    const float* data_te    = (const float*)d_in[1];
    const float* data_se    = (const float*)d_in[2];
    const float* h_n0 = (const float*)d_in[3];
    const float* c_n0 = (const float*)d_in[4];
    const float* h_t0 = (const float*)d_in[5];
    const float* c_t0 = (const float*)d_in[6];
    const float* h_s0 = (const float*)d_in[7];
    const float* c_s0 = (const float*)d_in[8];
    const int*   inc  = (const int*)d_in[9];
    const float* t_enc_w = (const float*)d_in[10];
    const float* t_enc_b = (const float*)d_in[11];
    const float* t_Wih   = (const float*)d_in[12];
    const float* t_Whh   = (const float*)d_in[13];
    const float* t_b     = (const float*)d_in[14];
    const float* s_enc_w = (const float*)d_in[15];
    const float* s_enc_b = (const float*)d_in[16];
    const float* s_Wih   = (const float*)d_in[17];
    const float* s_Whh   = (const float*)d_in[18];
    const float* s_b     = (const float*)d_in[19];
    const float* n_enc_w = (const float*)d_in[20];
    const float* n_enc_b = (const float*)d_in[21];
    const float* ee_w    = (const float*)d_in[22];
    const float* ee_b    = (const float*)d_in[23];
    const float* n_Wih   = (const float*)d_in[24];
    const float* n_Whh   = (const float*)d_in[25];
    const float* n_b     = (const float*)d_in[26];
    const float* out_w   = (const float*)d_in[27];
    const float* out_b   = (const float*)d_in[28];
    float* out = (float*)d_out;

    float *hs, *cs, *ht, *ct, *hn, *cn, *agg;
    __nv_bfloat16 *w2t_s, *w2t_t, *w2t_n;
    cudaGetSymbolAddress((void**)&hs,  g_hs);
    cudaGetSymbolAddress((void**)&cs,  g_cs);
    cudaGetSymbolAddress((void**)&ht,  g_ht);
    cudaGetSymbolAddress((void**)&ct,  g_ct);
    cudaGetSymbolAddress((void**)&hn,  g_hn);
    cudaGetSymbolAddress((void**)&cn,  g_cn);
    cudaGetSymbolAddress((void**)&agg, g_agg);
    cudaGetSymbolAddress((void**)&w2t_s, g_w2t_s);
    cudaGetSymbolAddress((void**)&w2t_t, g_w2t_t);
    cudaGetSymbolAddress((void**)&w2t_n, g_w2t_n);

    cudaMemcpyAsync(hs, h_s0, (size_t)EE * 64  * 4, cudaMemcpyDeviceToDevice);
    cudaMemcpyAsync(cs, c_s0, (size_t)EE * 64  * 4, cudaMemcpyDeviceToDevice);
    cudaMemcpyAsync(ht, h_t0, (size_t)NN * 64  * 4, cudaMemcpyDeviceToDevice);
    cudaMemcpyAsync(ct, c_t0, (size_t)NN * 64  * 4, cudaMemcpyDeviceToDevice);
    cudaMemcpyAsync(hn, h_n0, (size_t)NN * 128 * 4, cudaMemcpyDeviceToDevice);
    cudaMemcpyAsync(cn, c_n0, (size_t)NN * 128 * 4, cudaMemcpyDeviceToDevice);

    prep_edge_w<<<128, 256>>>(s_Wih, s_Whh, w2t_s);
    prep_edge_w<<<128, 256>>>(t_Wih, t_Whh, w2t_t);
    prep_node_w<<<512, 256>>>(n_Wih, n_Whh, w2t_n);

    cudaFuncSetAttribute(edge_mma_kernel, cudaFuncAttributeMaxDynamicSharedMemorySize, EDGE_SMEM);
    cudaFuncSetAttribute(node_mma_kernel, cudaFuncAttributeMaxDynamicSharedMemorySize, NODE_SMEM);

    for (int t = 0; t < SSTEPS; ++t) {
        cudaMemsetAsync(agg, 0, (size_t)NN * 64 * 4);
        edge_mma_kernel<<<EE / 64, 256, EDGE_SMEM>>>(data_se + (size_t)t * EE * 2,
                                                     s_enc_w, s_enc_b, w2t_s, s_b,
                                                     hs, cs, agg, inc);
        edge_mma_kernel<<<NN / 64, 256, EDGE_SMEM>>>(data_te + (size_t)t * NN * 2,
                                                     t_enc_w, t_enc_b, w2t_t, t_b,
                                                     ht, ct, nullptr, nullptr);
        node_mma_kernel<<<NN / 64, 256, NODE_SMEM>>>(
            data_nodes + (size_t)t * NN,
            n_enc_w, n_enc_b, ee_w, ee_b, w2t_n, n_b, out_w, out_b,
            ht, agg, hn, cn, out + (size_t)t * NN);
    }
}

// round 7
// speedup vs baseline: 1.3247x; 1.1737x over previous
#include <cuda_runtime.h>
#include <cuda_bf16.h>
#include <cstdint>

#define SSTEPS 16
#define NN 32768
#define EE 131072

// -------- persistent state (device globals; no allocation allowed) --------
__device__ float g_hs[(size_t)EE * 64];
__device__ float g_cs[(size_t)EE * 64];
__device__ float g_ht[(size_t)NN * 64];
__device__ float g_ct[(size_t)NN * 64];
__device__ float g_hn[(size_t)NN * 128];
__device__ float g_cn[(size_t)NN * 128];
__device__ float g_agg[(size_t)NN * 64];

// pre-split, gate-interleaved, n-major weights (bf16, k' = [hi | lo])
__device__ __nv_bfloat16 g_w2t_s[256 * 256];   // edge spatial: [rb=256][k'=256]
__device__ __nv_bfloat16 g_w2t_t[256 * 256];   // edge temporal
__device__ __nv_bfloat16 g_w2t_n[512 * 512];   // node: [rb=512][k'=512]

// node input planes: [enc(64) | emb(64) | hn_snapshot(128)] pre-split bf16
__device__ __nv_bfloat16 g_xeh[(size_t)NN * 256];
__device__ __nv_bfloat16 g_xel[(size_t)NN * 256];

__device__ __forceinline__ float sigf(float x)   { return 1.f / (1.f + __expf(-x)); }
__device__ __forceinline__ float tanh_f(float x) { return 2.f / (1.f + __expf(-2.f * x)) - 1.f; }

__device__ __forceinline__ void split_bf16(float v, __nv_bfloat16& hi, __nv_bfloat16& lo) {
    hi = __float2bfloat16(v);
    lo = __float2bfloat16(v - __bfloat162float(hi));
}

// split two adjacent values, store packed bf16x2 into hi/lo planes
__device__ __forceinline__ void split2_store(char* baseHi, char* baseLo, uint32_t off,
                                             float v0, float v1) {
    __nv_bfloat16 h0, l0, h1, l1;
    split_bf16(v0, h0, l0);
    split_bf16(v1, h1, l1);
    *(__nv_bfloat162*)(baseHi + off) = __halves2bfloat162(h0, h1);
    *(__nv_bfloat162*)(baseLo + off) = __halves2bfloat162(l0, l1);
}

__device__ __forceinline__ uint32_t smem_u32(const void* p) {
    return (uint32_t)__cvta_generic_to_shared(p);
}

#define LDSM4(r0, r1, r2, r3, addr) \
    asm volatile("ldmatrix.sync.aligned.m8n8.x4.shared.b16 {%0,%1,%2,%3},[%4];" \
                 : "=r"(r0), "=r"(r1), "=r"(r2), "=r"(r3) : "r"(addr))

#define MMA_BF16(D, a0, a1, a2, a3, b0, b1) \
    asm volatile("mma.sync.aligned.m16n8k16.row.col.f32.bf16.bf16.f32 " \
                 "{%0,%1,%2,%3},{%4,%5,%6,%7},{%8,%9},{%0,%1,%2,%3};" \
                 : "+f"(D[0]), "+f"(D[1]), "+f"(D[2]), "+f"(D[3]) \
                 : "r"(a0), "r"(a1), "r"(a2), "r"(a3), "r"(b0), "r"(b1))

#define CP16(saddr, gptr) \
    asm volatile("cp.async.cg.shared.global [%0],[%1],16;" :: "r"(saddr), "l"(gptr))
#define CP_COMMIT() asm volatile("cp.async.commit_group;")
#define CP_WAIT0()  asm volatile("cp.async.wait_group 0;")
#define CP_WAIT1()  asm volatile("cp.async.wait_group 1;")

// ============================================================================
// weight prep
// edge rb = wg*128 + g*32 + jj  -> orig_n = g*64 + wg*32 + jj
// ============================================================================
__global__ void prep_edge_w(const float* __restrict__ Wih, const float* __restrict__ Whh,
                            __nv_bfloat16* __restrict__ W2t) {
    int idx = blockIdx.x * 256 + threadIdx.x;   // 256 rb * 128 k
    int rb = idx >> 7, k = idx & 127;
    int wg = rb >> 7, g = (rb >> 5) & 3, jj = rb & 31;
    int orig_n = g * 64 + wg * 32 + jj;
    float v = (k < 64) ? Wih[k * 256 + orig_n] : Whh[(k - 64) * 256 + orig_n];
    __nv_bfloat16 hi, lo; split_bf16(v, hi, lo);
    W2t[rb * 256 + k] = hi;
    W2t[rb * 256 + 128 + k] = lo;
}

// node rb = nh*256 + nw*128 + g*32 + jj -> orig_n = g*128 + nh*64 + nw*32 + jj
__global__ void prep_node_w(const float* __restrict__ Wih, const float* __restrict__ Whh,
                            __nv_bfloat16* __restrict__ W2t) {
    int idx = blockIdx.x * 256 + threadIdx.x;   // 512 rb * 256 k
    int rb = idx >> 8, k = idx & 255;
    int nh = rb >> 8, nw = (rb >> 7) & 1, g = (rb >> 5) & 3, jj = rb & 31;
    int orig_n = g * 128 + nh * 64 + nw * 32 + jj;
    float v = (k < 128) ? Wih[k * 512 + orig_n] : Whh[(k - 128) * 512 + orig_n];
    __nv_bfloat16 hi, lo; split_bf16(v, hi, lo);
    W2t[rb * 512 + k] = hi;
    W2t[rb * 512 + 256 + k] = lo;
}

// ============================================================================
// Edge LSTM (hidden 64, K=128, N=256), weight-stationary mma.sync.
// Block = 128 rows, 8 warps (4M x 2N). Warp tile m32 x n128.
// SMEM (bf16, padded stride 136 elems = 272 B):
//   Ahi [128][136] 34816 | Alo 34816 | Bhi [256][136] 69632 | Blo 69632
// ============================================================================
#define E_AHI 0
#define E_ALO 34816
#define E_BHI 69632
#define E_BLO 139264
#define EDGE_SMEM 208896

__global__ __launch_bounds__(256, 1) void edge_mma2_kernel(
    const float* __restrict__ x,
    const float* __restrict__ encw, const float* __restrict__ encb,
    const __nv_bfloat16* __restrict__ W2t,
    const float* __restrict__ bias,
    float* __restrict__ h, float* __restrict__ c,
    float* __restrict__ agg, const int* __restrict__ inc)
{
    extern __shared__ char sm[];
    const uint32_t sb = smem_u32(sm);
    const int tid = threadIdx.x;
    const int wid = tid >> 5, l = tid & 31;
    const int mw = wid & 3, nw = wid >> 2;
    const int m0 = mw * 32;
    const int row0 = blockIdx.x * 128;

    // ---- stage B (both planes, once) ----
    #pragma unroll
    for (int it = 0; it < 32; ++it) {
        int idx = tid + it * 256;                 // 8192 x 16B
        int plane = idx >> 12;
        int i2 = idx & 4095;
        int r = i2 >> 4, k8 = i2 & 15;
        const __nv_bfloat16* src = W2t + (size_t)r * 256 + plane * 128 + k8 * 8;
        CP16(sb + (plane ? E_BLO : E_BHI) + r * 272 + k8 * 16, src);
    }
    CP_COMMIT();

    // ---- stage A (enc cols 0..63, h cols 64..127), split planes ----
    #pragma unroll
    for (int it = 0; it < 16; ++it) {
        int idx = tid + it * 256;                 // 4096 = 128r x 32 j4-groups
        int r = idx >> 5, j4 = idx & 31;
        int R = row0 + r;
        if (j4 < 16) {
            float x0 = x[R * 2 + 0], x1 = x[R * 2 + 1];
            int j = j4 * 4;
            #pragma unroll
            for (int e = 0; e < 2; ++e) {
                int cc = j + e * 2;
                float v0 = fmaxf(fmaf(x0, __ldg(&encw[cc]),     fmaf(x1, __ldg(&encw[64 + cc]),     __ldg(&encb[cc]))), 0.f);
                float v1 = fmaxf(fmaf(x0, __ldg(&encw[cc + 1]), fmaf(x1, __ldg(&encw[64 + cc + 1]), __ldg(&encb[cc + 1]))), 0.f);
                split2_store(sm + E_AHI, sm + E_ALO, r * 272 + cc * 2, v0, v1);
            }
        } else {
            int j = (j4 - 16) * 4;
            float4 hv = *(const float4*)&h[(size_t)R * 64 + j];
            split2_store(sm + E_AHI, sm + E_ALO, r * 272 + (64 + j) * 2, hv.x, hv.y);
            split2_store(sm + E_AHI, sm + E_ALO, r * 272 + (64 + j + 2) * 2, hv.z, hv.w);
        }
    }

    CP_WAIT0();
    __syncthreads();

    // ---- lane-constant offsets ----
    const int qi = l >> 3, ii = l & 7;
    const uint32_t b_lane = ((qi >= 2 ? 8u : 0u) + (uint32_t)ii) * 272u + (qi & 1) * 16u;
    const uint32_t a_lane = (uint32_t)(l & 15) * 272u + (uint32_t)(l >> 4) * 16u;
    const uint32_t aHiB = sb + E_AHI + m0 * 272 + a_lane;
    const uint32_t aLoB = sb + E_ALO + m0 * 272 + a_lane;
    const uint32_t bHiB = sb + E_BHI + nw * 34816 + b_lane;
    const uint32_t bLoB = sb + E_BLO + nw * 34816 + b_lane;

    float acc[2][16][4];
    #pragma unroll
    for (int mt = 0; mt < 2; ++mt)
        #pragma unroll
        for (int nt = 0; nt < 16; ++nt)
            #pragma unroll
            for (int e = 0; e < 4; ++e) acc[mt][nt][e] = 0.f;

    // ---- mainloop: B plane hi feeds Ahi+Alo; B plane lo feeds Ahi ----
    #pragma unroll
    for (int ph = 0; ph < 2; ++ph) {
        const uint32_t bB = ph ? bLoB : bHiB;
        #pragma unroll
        for (int ks = 0; ks < 8; ++ks) {
            uint32_t bb[16][2];
            #pragma unroll
            for (int fg = 0; fg < 8; ++fg) {
                uint32_t r0, r1, r2, r3;
                LDSM4(r0, r1, r2, r3, bB + fg * 4352 + ks * 32);
                bb[fg * 2][0] = r0;     bb[fg * 2][1] = r1;
                bb[fg * 2 + 1][0] = r2; bb[fg * 2 + 1][1] = r3;
            }
            #pragma unroll
            for (int ap = 0; ap < 2; ++ap) {
                if (ph == 1 && ap == 1) continue;   // lo B only pairs with Ahi
                #pragma unroll
                for (int mt = 0; mt < 2; ++mt) {
                    uint32_t a0, a1, a2, a3;
                    LDSM4(a0, a1, a2, a3, (ap ? aLoB : aHiB) + mt * 4352 + ks * 32);
                    #pragma unroll
                    for (int nt = 0; nt < 16; ++nt)
                        MMA_BF16(acc[mt][nt], a0, a1, a2, a3, bb[nt][0], bb[nt][1]);
                }
            }
        }
    }

    // ---- LSTM epilogue (+ optional scatter) ----
    const int rbase = row0 + m0 + (l >> 2);
    #pragma unroll
    for (int mt = 0; mt < 2; ++mt) {
        #pragma unroll
        for (int rh = 0; rh < 2; ++rh) {
            int R = rbase + mt * 16 + rh * 8;
            int n0 = 0, n1 = 0;
            if (agg) { n0 = inc[2 * R]; n1 = inc[2 * R + 1]; }
            #pragma unroll
            for (int q = 0; q < 4; ++q) {
                int j0 = nw * 32 + q * 8 + 2 * (l & 3);
                float i0 = acc[mt][q][rh * 2]          + __ldg(&bias[j0]);
                float i1 = acc[mt][q][rh * 2 + 1]      + __ldg(&bias[j0 + 1]);
                float f0 = acc[mt][4 + q][rh * 2]      + __ldg(&bias[64 + j0]);
                float f1 = acc[mt][4 + q][rh * 2 + 1]  + __ldg(&bias[64 + j0 + 1]);
                float g0 = acc[mt][8 + q][rh * 2]      + __ldg(&bias[128 + j0]);
                float g1 = acc[mt][8 + q][rh * 2 + 1]  + __ldg(&bias[128 + j0 + 1]);
                float o0 = acc[mt][12 + q][rh * 2]     + __ldg(&bias[192 + j0]);
                float o1 = acc[mt][12 + q][rh * 2 + 1] + __ldg(&bias[192 + j0 + 1]);
                float2 cold = *(const float2*)&c[(size_t)R * 64 + j0];
                float c0 = sigf(f0) * cold.x + sigf(i0) * tanh_f(g0);
                float c1 = sigf(f1) * cold.y + sigf(i1) * tanh_f(g1);
                float h0 = sigf(o0) * tanh_f(c0);
                float h1 = sigf(o1) * tanh_f(c1);
                *(float2*)&c[(size_t)R * 64 + j0] = make_float2(c0, c1);
                *(float2*)&h[(size_t)R * 64 + j0] = make_float2(h0, h1);
                if (agg) {
                    atomicAdd(&agg[(size_t)n0 * 64 + j0],     h0);
                    atomicAdd(&agg[(size_t)n0 * 64 + j0 + 1], h1);
                    atomicAdd(&agg[(size_t)n1 * 64 + j0],     h0);
                    atomicAdd(&agg[(size_t)n1 * 64 + j0 + 1], h1);
                }
            }
        }
    }
}

// ============================================================================
// emb kernel: enc = relu(xn*nencw+nencb); emb = relu([ht,agg]@eew+eeb);
// plus SNAPSHOT of hn (h_{t-1}) into the planes (fixes cross-block race).
// Planes g_xeh/g_xel [node][256]: enc 0..63 | emb 64..127 | hn 128..255.
// Block: 64 rows, 256 threads. fp32 compute.
// ============================================================================
#define EMB_SMEM (64 * 132 * 4 + 128 * 64 * 4)

__global__ __launch_bounds__(256) void emb_kernel(
    const float* __restrict__ xn,
    const float* __restrict__ nencw, const float* __restrict__ nencb,
    const float* __restrict__ eew,   const float* __restrict__ eeb,
    const float* __restrict__ ht,    const float* __restrict__ agg,
    const float* __restrict__ hn,
    __nv_bfloat16* __restrict__ xeh, __nv_bfloat16* __restrict__ xel)
{
    extern __shared__ float smf[];
    float* Asf  = smf;                 // [64][132]
    float* eewS = smf + 64 * 132;      // [128][64]

    const int tid = threadIdx.x;
    const int row0 = blockIdx.x * 64;

    #pragma unroll
    for (int it = 0; it < 16; ++it) {
        int idx = tid + it * 256;      // 4096 = 64r x 64j
        int r = idx >> 6, j = idx & 63;
        int R = row0 + r;
        Asf[r * 132 + j]      = ht[(size_t)R * 64 + j];
        Asf[r * 132 + 64 + j] = agg[(size_t)R * 64 + j];
    }
    #pragma unroll
    for (int it = 0; it < 8; ++it) {
        int f4 = tid + it * 256;
        *(float4*)&eewS[f4 * 4] = *(const float4*)&eew[f4 * 4];
    }

    // ---- hn snapshot (h_{t-1}) -> plane cols 128..255 ----
    #pragma unroll
    for (int it = 0; it < 16; ++it) {
        int idx = tid + it * 256;      // 4096 = 64r x 64 jpairs
        int r = idx >> 6, jp = idx & 63;
        int R = row0 + r;
        float2 hv = *(const float2*)&hn[(size_t)R * 128 + jp * 2];
        split2_store((char*)(xeh + (size_t)R * 256), (char*)(xel + (size_t)R * 256),
                     (128 + jp * 2) * 2, hv.x, hv.y);
    }
    __syncthreads();

    const int r = tid >> 2, jq = tid & 3;
    const int R = row0 + r;

    // enc cols jq*16..+16
    {
        float xv = xn[R];
        #pragma unroll
        for (int u = 0; u < 8; ++u) {
            int cc = jq * 16 + u * 2;
            float v0 = fmaxf(fmaf(xv, __ldg(&nencw[cc]),     __ldg(&nencb[cc])), 0.f);
            float v1 = fmaxf(fmaf(xv, __ldg(&nencw[cc + 1]), __ldg(&nencb[cc + 1])), 0.f);
            split2_store((char*)(xeh + (size_t)R * 256), (char*)(xel + (size_t)R * 256),
                         cc * 2, v0, v1);
        }
    }

    // emb cols jq*16..+16
    {
        float accv[16];
        #pragma unroll
        for (int u = 0; u < 16; ++u) accv[u] = __ldg(&eeb[jq * 16 + u]);
        #pragma unroll 4
        for (int k = 0; k < 128; ++k) {
            float a = Asf[r * 132 + k];
            #pragma unroll
            for (int g = 0; g < 4; ++g) {
                float4 w4 = *(const float4*)&eewS[k * 64 + jq * 16 + g * 4];
                accv[g*4+0] = fmaf(a, w4.x, accv[g*4+0]);
                accv[g*4+1] = fmaf(a, w4.y, accv[g*4+1]);
                accv[g*4+2] = fmaf(a, w4.z, accv[g*4+2]);
                accv[g*4+3] = fmaf(a, w4.w, accv[g*4+3]);
            }
        }
        #pragma unroll
        for (int u = 0; u < 8; ++u) {
            float v0 = fmaxf(accv[u * 2], 0.f);
            float v1 = fmaxf(accv[u * 2 + 1], 0.f);
            int cc = 64 + jq * 16 + u * 2;
            split2_store((char*)(xeh + (size_t)R * 256), (char*)(xel + (size_t)R * 256),
                         cc * 2, v0, v1);
        }
    }
}

// ============================================================================
// Node LSTM GEMM (hidden 128, K=256). Grid (NN/128, 2); block = 128 rows,
// N-half (256 weight rows). 8 warps 4M x 2N, warp tile m32 x n128.
// A staged entirely from immutable planes (cp.async group 0 — committed
// BEFORE B chunks so the ring's wait_group accounting covers it).
// SMEM: Ahi [128][264] 67584 | Alo 67584 | 3x Bbuf [256][40] 20480
// ============================================================================
#define N_AHI 0
#define N_ALO 67584
#define N_BUF 135168
#define N_BUFSZ 20480
#define NODE_SMEM (135168 + 3 * 20480)

__global__ __launch_bounds__(256, 1) void node_mma2_kernel(
    const __nv_bfloat16* __restrict__ xeh, const __nv_bfloat16* __restrict__ xel,
    const __nv_bfloat16* __restrict__ W2t,
    const float* __restrict__ bias,
    const float* __restrict__ outw,  const float* __restrict__ outb,
    float* __restrict__ hn, float* __restrict__ cn,
    float* __restrict__ out)
{
    extern __shared__ char sm[];
    const uint32_t sb = smem_u32(sm);
    const int tid = threadIdx.x;
    const int wid = tid >> 5, l = tid & 31;
    const int mw = wid & 3, nw = wid >> 2;
    const int m0 = mw * 32;
    const int row0 = blockIdx.x * 128;
    const int nh = blockIdx.y;
    const __nv_bfloat16* Wb = W2t + (size_t)(nh * 256) * 512;

    // ---- stage A: full 256 cols from pre-split planes (group 0) ----
    #pragma unroll
    for (int it = 0; it < 32; ++it) {
        int idx = tid + it * 256;   // 8192: 2 planes x 128r x 32k8
        int plane = idx >> 12;
        int i2 = idx & 4095;
        int r = i2 >> 5, k8 = i2 & 31;
        const __nv_bfloat16* src = (plane ? xel : xeh) + (size_t)(row0 + r) * 256 + k8 * 8;
        CP16(sb + (plane ? N_ALO : N_AHI) + r * 528 + k8 * 16, src);
    }
    CP_COMMIT();

    // ---- preload B chunks 0,1 (groups 1,2) ----
    #pragma unroll
    for (int it = 0; it < 4; ++it) {
        int idx = tid + it * 256;   // 1024 = 256r x 4k8
        int r = idx >> 2, k8 = idx & 3;
        CP16(sb + N_BUF + r * 80 + k8 * 16, Wb + (size_t)r * 512 + 0 * 32 + k8 * 8);
    }
    CP_COMMIT();
    #pragma unroll
    for (int it = 0; it < 4; ++it) {
        int idx = tid + it * 256;
        int r = idx >> 2, k8 = idx & 3;
        CP16(sb + N_BUF + N_BUFSZ + r * 80 + k8 * 16, Wb + (size_t)r * 512 + 1 * 32 + k8 * 8);
    }
    CP_COMMIT();

    // lane-constant offsets
    const int qi = l >> 3, ii = l & 7;
    const uint32_t b_lane = ((qi >= 2 ? 8u : 0u) + (uint32_t)ii) * 80u + (qi & 1) * 16u;
    const uint32_t a_lane = (uint32_t)(l & 15) * 528u + (uint32_t)(l >> 4) * 16u;
    const uint32_t aHiB = sb + N_AHI + m0 * 528 + a_lane;
    const uint32_t aLoB = sb + N_ALO + m0 * 528 + a_lane;

    float acc[2][16][4];
    #pragma unroll
    for (int mt = 0; mt < 2; ++mt)
        #pragma unroll
        for (int nt = 0; nt < 16; ++nt)
            #pragma unroll
            for (int e = 0; e < 4; ++e) acc[mt][nt][e] = 0.f;

    // ---- mainloop: 16 chunks of k32 (phys: hi 0..7, lo 8..15) ----
    for (int cc = 0; cc < 16; ++cc) {
        if (cc < 15) { CP_WAIT1(); } else { CP_WAIT0(); }
        __syncthreads();

        const uint32_t bufB = sb + N_BUF + (cc % 3) * N_BUFSZ + nw * 10240 + b_lane;
        const bool hiChunk = (cc < 8);
        const uint32_t acol = (uint32_t)(cc & 7) * 64;   // A byte offset for this chunk

        #pragma unroll
        for (int ks2 = 0; ks2 < 2; ++ks2) {
            uint32_t bb[16][2];
            #pragma unroll
            for (int fg = 0; fg < 8; ++fg) {
                uint32_t r0, r1, r2, r3;
                LDSM4(r0, r1, r2, r3, bufB + fg * 1280 + ks2 * 32);
                bb[fg * 2][0] = r0;     bb[fg * 2][1] = r1;
                bb[fg * 2 + 1][0] = r2; bb[fg * 2 + 1][1] = r3;
            }
            #pragma unroll
            for (int ap = 0; ap < 2; ++ap) {
                if (!hiChunk && ap == 1) continue;
                #pragma unroll
                for (int mt = 0; mt < 2; ++mt) {
                    uint32_t a0, a1, a2, a3;
                    LDSM4(a0, a1, a2, a3,
                          (ap ? aLoB : aHiB) + mt * 8448 + acol + ks2 * 32);
                    #pragma unroll
                    for (int nt = 0; nt < 16; ++nt)
                        MMA_BF16(acc[mt][nt], a0, a1, a2, a3, bb[nt][0], bb[nt][1]);
                }
            }
        }

        if (cc + 2 < 16) {
            const int cn2 = cc + 2;
            const uint32_t dstb = sb + N_BUF + (cn2 % 3) * N_BUFSZ;
            #pragma unroll
            for (int it = 0; it < 4; ++it) {
                int idx = tid + it * 256;
                int r = idx >> 2, k8 = idx & 3;
                CP16(dstb + r * 80 + k8 * 16, Wb + (size_t)r * 512 + cn2 * 32 + k8 * 8);
            }
            CP_COMMIT();
        }
    }

    // ---- LSTM epilogue + out reduction ----
    const float ob = (nh == 0 && nw == 0) ? __ldg(outb) : 0.f;
    const int rbase = row0 + m0 + (l >> 2);
    #pragma unroll
    for (int mt = 0; mt < 2; ++mt) {
        #pragma unroll
        for (int rh = 0; rh < 2; ++rh) {
            int R = rbase + mt * 16 + rh * 8;
            float po = 0.f;
            #pragma unroll
            for (int q = 0; q < 4; ++q) {
                int j0 = nh * 64 + nw * 32 + q * 8 + 2 * (l & 3);
                float i0 = acc[mt][q][rh * 2]          + __ldg(&bias[j0]);
                float i1 = acc[mt][q][rh * 2 + 1]      + __ldg(&bias[j0 + 1]);
                float f0 = acc[mt][4 + q][rh * 2]      + __ldg(&bias[128 + j0]);
                float f1 = acc[mt][4 + q][rh * 2 + 1]  + __ldg(&bias[128 + j0 + 1]);
                float g0 = acc[mt][8 + q][rh * 2]      + __ldg(&bias[256 + j0]);
                float g1 = acc[mt][8 + q][rh * 2 + 1]  + __ldg(&bias[256 + j0 + 1]);
                float o0 = acc[mt][12 + q][rh * 2]     + __ldg(&bias[384 + j0]);
                float o1 = acc[mt][12 + q][rh * 2 + 1] + __ldg(&bias[384 + j0 + 1]);
                float2 cold = *(const float2*)&cn[(size_t)R * 128 + j0];
                float c0 = sigf(f0) * cold.x + sigf(i0) * tanh_f(g0);
                float c1 = sigf(f1) * cold.y + sigf(i1) * tanh_f(g1);
                float h0 = sigf(o0) * tanh_f(c0);
                float h1 = sigf(o1) * tanh_f(c1);
                *(float2*)&cn[(size_t)R * 128 + j0] = make_float2(c0, c1);
                *(float2*)&hn[(size_t)R * 128 + j0] = make_float2(h0, h1);
                po = fmaf(h0, __ldg(&outw[j0]), po);
                po = fmaf(h1, __ldg(&outw[j0 + 1]), po);
            }
            po += __shfl_xor_sync(0xffffffffu, po, 1);
            po += __shfl_xor_sync(0xffffffffu, po, 2);
            if ((l & 3) == 0) atomicAdd(&out[R], po + ob);
        }
    }
}

// ============================================================================
extern "C" void kernel_launch(void* const* d_in, const int* in_sizes, int n_in,
                              void* d_out, int out_size) {
    const float* data_nodes = (const float*)d_in[0];
    const float* data_te    = (const float*)d_in[1];
    const float* data_se    = (const float*)d_in[2];
    const float* h_n0 = (const float*)d_in[3];
    const float* c_n0 = (const float*)d_in[4];
    const float* h_t0 = (const float*)d_in[5];
    const float* c_t0 = (const float*)d_in[6];
    const float* h_s0 = (const float*)d_in[7];
    const float* c_s0 = (const float*)d_in[8];
    const int*   inc  = (const int*)d_in[9];
    const float* t_enc_w = (const float*)d_in[10];
    const float* t_enc_b = (const float*)d_in[11];
    const float* t_Wih   = (const float*)d_in[12];
    const float* t_Whh   = (const float*)d_in[13];
    const float* t_b     = (const float*)d_in[14];
    const float* s_enc_w = (const float*)d_in[15];
    const float* s_enc_b = (const float*)d_in[16];
    const float* s_Wih   = (const float*)d_in[17];
    const float* s_Whh   = (const float*)d_in[18];
    const float* s_b     = (const float*)d_in[19];
    const float* n_enc_w = (const float*)d_in[20];
    const float* n_enc_b = (const float*)d_in[21];
    const float* ee_w    = (const float*)d_in[22];
    const float* ee_b    = (const float*)d_in[23];
    const float* n_Wih   = (const float*)d_in[24];
    const float* n_Whh   = (const float*)d_in[25];
    const float* n_b     = (const float*)d_in[26];
    const float* out_w   = (const float*)d_in[27];
    const float* out_b   = (const float*)d_in[28];
    float* out = (float*)d_out;

    float *hs, *cs, *ht, *ct, *hn, *cn, *agg;
    __nv_bfloat16 *w2t_s, *w2t_t, *w2t_n, *xeh, *xel;
    cudaGetSymbolAddress((void**)&hs,  g_hs);
    cudaGetSymbolAddress((void**)&cs,  g_cs);
    cudaGetSymbolAddress((void**)&ht,  g_ht);
    cudaGetSymbolAddress((void**)&ct,  g_ct);
    cudaGetSymbolAddress((void**)&hn,  g_hn);
    cudaGetSymbolAddress((void**)&cn,  g_cn);
    cudaGetSymbolAddress((void**)&agg, g_agg);
    cudaGetSymbolAddress((void**)&w2t_s, g_w2t_s);
    cudaGetSymbolAddress((void**)&w2t_t, g_w2t_t);
    cudaGetSymbolAddress((void**)&w2t_n, g_w2t_n);
    cudaGetSymbolAddress((void**)&xeh, g_xeh);
    cudaGetSymbolAddress((void**)&xel, g_xel);

    cudaMemcpyAsync(hs, h_s0, (size_t)EE * 64  * 4, cudaMemcpyDeviceToDevice);
    cudaMemcpyAsync(cs, c_s0, (size_t)EE * 64  * 4, cudaMemcpyDeviceToDevice);
    cudaMemcpyAsync(ht, h_t0, (size_t)NN * 64  * 4, cudaMemcpyDeviceToDevice);
    cudaMemcpyAsync(ct, c_t0, (size_t)NN * 64  * 4, cudaMemcpyDeviceToDevice);
    cudaMemcpyAsync(hn, h_n0, (size_t)NN * 128 * 4, cudaMemcpyDeviceToDevice);
    cudaMemcpyAsync(cn, c_n0, (size_t)NN * 128 * 4, cudaMemcpyDeviceToDevice);
    cudaMemsetAsync(out, 0, (size_t)SSTEPS * NN * 4);

    prep_edge_w<<<128, 256>>>(s_Wih, s_Whh, w2t_s);
    prep_edge_w<<<128, 256>>>(t_Wih, t_Whh, w2t_t);
    prep_node_w<<<512, 256>>>(n_Wih, n_Whh, w2t_n);

    cudaFuncSetAttribute(edge_mma2_kernel, cudaFuncAttributeMaxDynamicSharedMemorySize, EDGE_SMEM);
    cudaFuncSetAttribute(node_mma2_kernel, cudaFuncAttributeMaxDynamicSharedMemorySize, NODE_SMEM);
    cudaFuncSetAttribute(emb_kernel,       cudaFuncAttributeMaxDynamicSharedMemorySize, EMB_SMEM);

    for (int t = 0; t < SSTEPS; ++t) {
        cudaMemsetAsync(agg, 0, (size_t)NN * 64 * 4);
        edge_mma2_kernel<<<EE / 128, 256, EDGE_SMEM>>>(data_se + (size_t)t * EE * 2,
                                                       s_enc_w, s_enc_b, w2t_s, s_b,
                                                       hs, cs, agg, inc);
        edge_mma2_kernel<<<NN / 128, 256, EDGE_SMEM>>>(data_te + (size_t)t * NN * 2,
                                                       t_enc_w, t_enc_b, w2t_t, t_b,
                                                       ht, ct, nullptr, nullptr);
        emb_kernel<<<NN / 64, 256, EMB_SMEM>>>(data_nodes + (size_t)t * NN,
                                               n_enc_w, n_enc_b, ee_w, ee_b,
                                               ht, agg, hn, xeh, xel);
        node_mma2_kernel<<<dim3(NN / 128, 2), 256, NODE_SMEM>>>(
            xeh, xel, w2t_n, n_b, out_w, out_b,
            hn, cn, out + (size_t)t * NN);
    }
}

// round 8
// speedup vs baseline: 1.7881x; 1.3498x over previous
#include <cuda_runtime.h>
#include <cuda_bf16.h>
#include <cstdint>

#define SSTEPS 16
#define NN 32768
#define EE 131072

// -------- persistent state (device globals; no allocation allowed) --------
__device__ float g_hs[(size_t)EE * 64];
__device__ float g_cs[(size_t)EE * 64];
__device__ float g_ht[(size_t)NN * 64];
__device__ float g_ct[(size_t)NN * 64];
__device__ float g_hn[(size_t)NN * 128];
__device__ float g_cn[(size_t)NN * 128];
__device__ float g_agg[(size_t)NN * 64];

// pre-split, gate-interleaved, n-major weights (bf16, k' = [hi | lo])
__device__ __nv_bfloat16 g_w2t_s[256 * 256];   // edge spatial: [rb=256][k'=256]
__device__ __nv_bfloat16 g_w2t_t[256 * 256];   // edge temporal
__device__ __nv_bfloat16 g_w2t_n[512 * 512];   // node: [rb=512][k'=512]

// node input planes: [enc(64) | emb(64) | hn_snapshot(128)] pre-split bf16
__device__ __nv_bfloat16 g_xeh[(size_t)NN * 256];
__device__ __nv_bfloat16 g_xel[(size_t)NN * 256];

__device__ __forceinline__ float sigf(float x)   { return 1.f / (1.f + __expf(-x)); }
__device__ __forceinline__ float tanh_f(float x) { return 2.f / (1.f + __expf(-2.f * x)) - 1.f; }

__device__ __forceinline__ void split_bf16(float v, __nv_bfloat16& hi, __nv_bfloat16& lo) {
    hi = __float2bfloat16(v);
    lo = __float2bfloat16(v - __bfloat162float(hi));
}

__device__ __forceinline__ void split2_store(char* baseHi, char* baseLo, uint32_t off,
                                             float v0, float v1) {
    __nv_bfloat16 h0, l0, h1, l1;
    split_bf16(v0, h0, l0);
    split_bf16(v1, h1, l1);
    *(__nv_bfloat162*)(baseHi + off) = __halves2bfloat162(h0, h1);
    *(__nv_bfloat162*)(baseLo + off) = __halves2bfloat162(l0, l1);
}

__device__ __forceinline__ uint32_t smem_u32(const void* p) {
    return (uint32_t)__cvta_generic_to_shared(p);
}

#define LDSM4(r0, r1, r2, r3, addr) \
    asm volatile("ldmatrix.sync.aligned.m8n8.x4.shared.b16 {%0,%1,%2,%3},[%4];" \
                 : "=r"(r0), "=r"(r1), "=r"(r2), "=r"(r3) : "r"(addr))

#define MMA_BF16(D, a0, a1, a2, a3, b0, b1) \
    asm volatile("mma.sync.aligned.m16n8k16.row.col.f32.bf16.bf16.f32 " \
                 "{%0,%1,%2,%3},{%4,%5,%6,%7},{%8,%9},{%0,%1,%2,%3};" \
                 : "+f"(D[0]), "+f"(D[1]), "+f"(D[2]), "+f"(D[3]) \
                 : "r"(a0), "r"(a1), "r"(a2), "r"(a3), "r"(b0), "r"(b1))

#define CP16(saddr, gptr) \
    asm volatile("cp.async.cg.shared.global [%0],[%1],16;" :: "r"(saddr), "l"(gptr))
#define CP_COMMIT() asm volatile("cp.async.commit_group;")
#define CP_WAIT0()  asm volatile("cp.async.wait_group 0;")
#define CP_WAIT1()  asm volatile("cp.async.wait_group 1;")

// ============================================================================
// weight prep (gate-interleaved for 4 N-warps of n64)
// edge rb = nw*64 + g*16 + jj  -> orig_n = g*64 + nw*16 + jj
// ============================================================================
__global__ void prep_edge_w(const float* __restrict__ Wih, const float* __restrict__ Whh,
                            __nv_bfloat16* __restrict__ W2t) {
    int idx = blockIdx.x * 256 + threadIdx.x;   // 256 rb * 128 k
    int rb = idx >> 7, k = idx & 127;
    int nw = rb >> 6, g = (rb >> 4) & 3, jj = rb & 15;
    int orig_n = g * 64 + nw * 16 + jj;
    float v = (k < 64) ? Wih[k * 256 + orig_n] : Whh[(k - 64) * 256 + orig_n];
    __nv_bfloat16 hi, lo; split_bf16(v, hi, lo);
    W2t[rb * 256 + k] = hi;
    W2t[rb * 256 + 128 + k] = lo;
}

// node rb = nh*256 + nw*64 + g*16 + jj -> orig_n = g*128 + nh*64 + nw*16 + jj
__global__ void prep_node_w(const float* __restrict__ Wih, const float* __restrict__ Whh,
                            __nv_bfloat16* __restrict__ W2t) {
    int idx = blockIdx.x * 256 + threadIdx.x;   // 512 rb * 256 k
    int rb = idx >> 8, k = idx & 255;
    int nh = rb >> 8, nw = (rb >> 6) & 3, g = (rb >> 4) & 3, jj = rb & 15;
    int orig_n = g * 128 + nh * 64 + nw * 16 + jj;
    float v = (k < 128) ? Wih[k * 512 + orig_n] : Whh[(k - 128) * 512 + orig_n];
    __nv_bfloat16 hi, lo; split_bf16(v, hi, lo);
    W2t[rb * 512 + k] = hi;
    W2t[rb * 512 + 256 + k] = lo;
}

// ============================================================================
// Edge LSTM (hidden 64, K=128, N=256), merged spatial+temporal.
// Block = 64 rows, 8 warps (2M x 4N), warp tile m32 x n64, 2 blocks/SM.
// SMEM: Ahi [64][136] 17408 | Alo 17408 | 3x Bbuf [256][40] 20480
// B streamed in 8 k32 chunks (hi 0..3, lo 4..7) of the [256][256] weights.
// ============================================================================
#define E_AHI 0
#define E_ALO 17408
#define E_BUF 34816
#define E_BUFSZ 20480
#define EDGE_SMEM (34816 + 3 * 20480)
#define SE_BLOCKS (EE / 64)

__global__ __launch_bounds__(256, 2) void edge_mma3_kernel(
    const float* __restrict__ x_s, const float* __restrict__ x_t,
    const float* __restrict__ encw_s, const float* __restrict__ encb_s,
    const float* __restrict__ encw_t, const float* __restrict__ encb_t,
    const __nv_bfloat16* __restrict__ W2t_s, const __nv_bfloat16* __restrict__ W2t_t,
    const float* __restrict__ bias_s, const float* __restrict__ bias_t,
    float* __restrict__ h_s, float* __restrict__ c_s,
    float* __restrict__ h_t, float* __restrict__ c_t,
    float* __restrict__ agg, const int* __restrict__ inc)
{
    extern __shared__ char sm[];
    const uint32_t sb = smem_u32(sm);
    const int tid = threadIdx.x;
    const int wid = tid >> 5, l = tid & 31;
    const int mw = wid & 1, nw = wid >> 1;
    const int m0 = mw * 32;

    const bool is_se = (blockIdx.x < SE_BLOCKS);
    const int row0 = (is_se ? blockIdx.x : (blockIdx.x - SE_BLOCKS)) * 64;
    const float* x    = is_se ? x_s : x_t;
    const float* encw = is_se ? encw_s : encw_t;
    const float* encb = is_se ? encb_s : encb_t;
    const __nv_bfloat16* W2t = is_se ? W2t_s : W2t_t;
    const float* bias = is_se ? bias_s : bias_t;
    float* h = is_se ? h_s : h_t;
    float* c = is_se ? c_s : c_t;
    float* aggp = is_se ? agg : nullptr;

    // ---- preload B chunks 0,1 ----
    #pragma unroll
    for (int it = 0; it < 4; ++it) {
        int idx = tid + it * 256;                 // 1024 = 256r x 4k8
        int r = idx >> 2, k8 = idx & 3;
        CP16(sb + E_BUF + r * 80 + k8 * 16, W2t + (size_t)r * 256 + 0 * 32 + k8 * 8);
    }
    CP_COMMIT();
    #pragma unroll
    for (int it = 0; it < 4; ++it) {
        int idx = tid + it * 256;
        int r = idx >> 2, k8 = idx & 3;
        CP16(sb + E_BUF + E_BUFSZ + r * 80 + k8 * 16, W2t + (size_t)r * 256 + 1 * 32 + k8 * 8);
    }
    CP_COMMIT();

    // ---- stage A (enc cols 0..63, h cols 64..127), split planes ----
    #pragma unroll
    for (int it = 0; it < 8; ++it) {
        int idx = tid + it * 256;                 // 2048 = 64r x 32 j4-groups
        int r = idx >> 5, j4 = idx & 31;
        int R = row0 + r;
        if (j4 < 16) {
            float x0 = x[R * 2 + 0], x1 = x[R * 2 + 1];
            int j = j4 * 4;
            #pragma unroll
            for (int e = 0; e < 2; ++e) {
                int cc = j + e * 2;
                float v0 = fmaxf(fmaf(x0, __ldg(&encw[cc]),     fmaf(x1, __ldg(&encw[64 + cc]),     __ldg(&encb[cc]))), 0.f);
                float v1 = fmaxf(fmaf(x0, __ldg(&encw[cc + 1]), fmaf(x1, __ldg(&encw[64 + cc + 1]), __ldg(&encb[cc + 1]))), 0.f);
                split2_store(sm + E_AHI, sm + E_ALO, r * 272 + cc * 2, v0, v1);
            }
        } else {
            int j = (j4 - 16) * 4;
            float4 hv = *(const float4*)&h[(size_t)R * 64 + j];
            split2_store(sm + E_AHI, sm + E_ALO, r * 272 + (64 + j) * 2, hv.x, hv.y);
            split2_store(sm + E_AHI, sm + E_ALO, r * 272 + (64 + j + 2) * 2, hv.z, hv.w);
        }
    }

    // ---- lane-constant offsets ----
    const int qi = l >> 3, ii = l & 7;
    const uint32_t b_lane = ((qi >= 2 ? 8u : 0u) + (uint32_t)ii) * 80u + (qi & 1) * 16u;
    const uint32_t a_lane = (uint32_t)(l & 15) * 272u + (uint32_t)(l >> 4) * 16u;
    const uint32_t aHiB = sb + E_AHI + m0 * 272 + a_lane;
    const uint32_t aLoB = sb + E_ALO + m0 * 272 + a_lane;
    const uint32_t bWarp = nw * 5120 + b_lane;      // nw*64 rows * 80B

    float acc[2][8][4];
    #pragma unroll
    for (int mt = 0; mt < 2; ++mt)
        #pragma unroll
        for (int nt = 0; nt < 8; ++nt)
            #pragma unroll
            for (int e = 0; e < 4; ++e) acc[mt][nt][e] = 0.f;

    // ---- mainloop: 8 k32 chunks (hi 0..3, lo 4..7) ----
    for (int cc = 0; cc < 8; ++cc) {
        if (cc < 7) { CP_WAIT1(); } else { CP_WAIT0(); }
        __syncthreads();

        if (cc + 2 < 8) {
            const int cn2 = cc + 2;
            const uint32_t dstb = sb + E_BUF + (cn2 % 3) * E_BUFSZ;
            #pragma unroll
            for (int it = 0; it < 4; ++it) {
                int idx = tid + it * 256;
                int r = idx >> 2, k8 = idx & 3;
                CP16(dstb + r * 80 + k8 * 16, W2t + (size_t)r * 256 + cn2 * 32 + k8 * 8);
            }
            CP_COMMIT();
        }

        const uint32_t bufB = sb + E_BUF + (cc % 3) * E_BUFSZ + bWarp;
        const bool hiChunk = (cc < 4);
        const uint32_t acol = (uint32_t)(cc & 3) * 64;

        #pragma unroll
        for (int ks2 = 0; ks2 < 2; ++ks2) {
            uint32_t bb[8][2];
            #pragma unroll
            for (int fg = 0; fg < 4; ++fg) {
                uint32_t r0, r1, r2, r3;
                LDSM4(r0, r1, r2, r3, bufB + fg * 1280 + ks2 * 32);
                bb[fg * 2][0] = r0;     bb[fg * 2][1] = r1;
                bb[fg * 2 + 1][0] = r2; bb[fg * 2 + 1][1] = r3;
            }
            #pragma unroll
            for (int ap = 0; ap < 2; ++ap) {
                if (!hiChunk && ap == 1) continue;
                #pragma unroll
                for (int mt = 0; mt < 2; ++mt) {
                    uint32_t a0, a1, a2, a3;
                    LDSM4(a0, a1, a2, a3, (ap ? aLoB : aHiB) + mt * 4352 + acol + ks2 * 32);
                    #pragma unroll
                    for (int nt = 0; nt < 8; ++nt)
                        MMA_BF16(acc[mt][nt], a0, a1, a2, a3, bb[nt][0], bb[nt][1]);
                }
            }
        }
    }

    // ---- LSTM epilogue (+ optional scatter) ----
    const int rbase = row0 + m0 + (l >> 2);
    #pragma unroll
    for (int mt = 0; mt < 2; ++mt) {
        #pragma unroll
        for (int rh = 0; rh < 2; ++rh) {
            int R = rbase + mt * 16 + rh * 8;
            int n0 = 0, n1 = 0;
            if (aggp) { n0 = inc[2 * R]; n1 = inc[2 * R + 1]; }
            #pragma unroll
            for (int u = 0; u < 2; ++u) {
                int j0 = nw * 16 + u * 8 + 2 * (l & 3);
                float i0 = acc[mt][u][rh * 2]          + __ldg(&bias[j0]);
                float i1 = acc[mt][u][rh * 2 + 1]      + __ldg(&bias[j0 + 1]);
                float f0 = acc[mt][2 + u][rh * 2]      + __ldg(&bias[64 + j0]);
                float f1 = acc[mt][2 + u][rh * 2 + 1]  + __ldg(&bias[64 + j0 + 1]);
                float g0 = acc[mt][4 + u][rh * 2]      + __ldg(&bias[128 + j0]);
                float g1 = acc[mt][4 + u][rh * 2 + 1]  + __ldg(&bias[128 + j0 + 1]);
                float o0 = acc[mt][6 + u][rh * 2]      + __ldg(&bias[192 + j0]);
                float o1 = acc[mt][6 + u][rh * 2 + 1]  + __ldg(&bias[192 + j0 + 1]);
                float2 cold = *(const float2*)&c[(size_t)R * 64 + j0];
                float c0 = sigf(f0) * cold.x + sigf(i0) * tanh_f(g0);
                float c1 = sigf(f1) * cold.y + sigf(i1) * tanh_f(g1);
                float h0 = sigf(o0) * tanh_f(c0);
                float h1 = sigf(o1) * tanh_f(c1);
                *(float2*)&c[(size_t)R * 64 + j0] = make_float2(c0, c1);
                *(float2*)&h[(size_t)R * 64 + j0] = make_float2(h0, h1);
                if (aggp) {
                    atomicAdd(&aggp[(size_t)n0 * 64 + j0],     h0);
                    atomicAdd(&aggp[(size_t)n0 * 64 + j0 + 1], h1);
                    atomicAdd(&aggp[(size_t)n1 * 64 + j0],     h0);
                    atomicAdd(&aggp[(size_t)n1 * 64 + j0 + 1], h1);
                }
            }
        }
    }
}

// ============================================================================
// emb kernel: enc/emb + hn snapshot into planes (unchanged from R7).
// ============================================================================
#define EMB_SMEM (64 * 132 * 4 + 128 * 64 * 4)

__global__ __launch_bounds__(256) void emb_kernel(
    const float* __restrict__ xn,
    const float* __restrict__ nencw, const float* __restrict__ nencb,
    const float* __restrict__ eew,   const float* __restrict__ eeb,
    const float* __restrict__ ht,    const float* __restrict__ agg,
    const float* __restrict__ hn,
    __nv_bfloat16* __restrict__ xeh, __nv_bfloat16* __restrict__ xel)
{
    extern __shared__ float smf[];
    float* Asf  = smf;                 // [64][132]
    float* eewS = smf + 64 * 132;      // [128][64]

    const int tid = threadIdx.x;
    const int row0 = blockIdx.x * 64;

    #pragma unroll
    for (int it = 0; it < 16; ++it) {
        int idx = tid + it * 256;
        int r = idx >> 6, j = idx & 63;
        int R = row0 + r;
        Asf[r * 132 + j]      = ht[(size_t)R * 64 + j];
        Asf[r * 132 + 64 + j] = agg[(size_t)R * 64 + j];
    }
    #pragma unroll
    for (int it = 0; it < 8; ++it) {
        int f4 = tid + it * 256;
        *(float4*)&eewS[f4 * 4] = *(const float4*)&eew[f4 * 4];
    }

    #pragma unroll
    for (int it = 0; it < 16; ++it) {
        int idx = tid + it * 256;
        int r = idx >> 6, jp = idx & 63;
        int R = row0 + r;
        float2 hv = *(const float2*)&hn[(size_t)R * 128 + jp * 2];
        split2_store((char*)(xeh + (size_t)R * 256), (char*)(xel + (size_t)R * 256),
                     (128 + jp * 2) * 2, hv.x, hv.y);
    }
    __syncthreads();

    const int r = tid >> 2, jq = tid & 3;
    const int R = row0 + r;

    {
        float xv = xn[R];
        #pragma unroll
        for (int u = 0; u < 8; ++u) {
            int cc = jq * 16 + u * 2;
            float v0 = fmaxf(fmaf(xv, __ldg(&nencw[cc]),     __ldg(&nencb[cc])), 0.f);
            float v1 = fmaxf(fmaf(xv, __ldg(&nencw[cc + 1]), __ldg(&nencb[cc + 1])), 0.f);
            split2_store((char*)(xeh + (size_t)R * 256), (char*)(xel + (size_t)R * 256),
                         cc * 2, v0, v1);
        }
    }

    {
        float accv[16];
        #pragma unroll
        for (int u = 0; u < 16; ++u) accv[u] = __ldg(&eeb[jq * 16 + u]);
        #pragma unroll 4
        for (int k = 0; k < 128; ++k) {
            float a = Asf[r * 132 + k];
            #pragma unroll
            for (int g = 0; g < 4; ++g) {
                float4 w4 = *(const float4*)&eewS[k * 64 + jq * 16 + g * 4];
                accv[g*4+0] = fmaf(a, w4.x, accv[g*4+0]);
                accv[g*4+1] = fmaf(a, w4.y, accv[g*4+1]);
                accv[g*4+2] = fmaf(a, w4.z, accv[g*4+2]);
                accv[g*4+3] = fmaf(a, w4.w, accv[g*4+3]);
            }
        }
        #pragma unroll
        for (int u = 0; u < 8; ++u) {
            float v0 = fmaxf(accv[u * 2], 0.f);
            float v1 = fmaxf(accv[u * 2 + 1], 0.f);
            int cc = 64 + jq * 16 + u * 2;
            split2_store((char*)(xeh + (size_t)R * 256), (char*)(xel + (size_t)R * 256),
                         cc * 2, v0, v1);
        }
    }
}

// ============================================================================
// Node LSTM GEMM (hidden 128, K=256). Grid (NN/64, 2); block = 64 rows,
// N-half. 8 warps 2M x 4N, warp tile m32 x n64, 2 blocks/SM.
// SMEM: Ahi [64][264] 33792 | Alo 33792 | 3x Bbuf [256][24] 12288
// B streamed in 32 k16 chunks (hi 0..15, lo 16..31).
// ============================================================================
#define N_AHI 0
#define N_ALO 33792
#define N_BUF 67584
#define N_BUFSZ 12288
#define NODE_SMEM (67584 + 3 * 12288)

__global__ __launch_bounds__(256, 2) void node_mma3_kernel(
    const __nv_bfloat16* __restrict__ xeh, const __nv_bfloat16* __restrict__ xel,
    const __nv_bfloat16* __restrict__ W2t,
    const float* __restrict__ bias,
    const float* __restrict__ outw,  const float* __restrict__ outb,
    float* __restrict__ hn, float* __restrict__ cn,
    float* __restrict__ out)
{
    extern __shared__ char sm[];
    const uint32_t sb = smem_u32(sm);
    const int tid = threadIdx.x;
    const int wid = tid >> 5, l = tid & 31;
    const int mw = wid & 1, nw = wid >> 1;
    const int m0 = mw * 32;
    const int row0 = blockIdx.x * 64;
    const int nh = blockIdx.y;
    const __nv_bfloat16* Wb = W2t + (size_t)(nh * 256) * 512;

    // ---- stage A: 256 cols from pre-split planes (group 0) ----
    #pragma unroll
    for (int it = 0; it < 16; ++it) {
        int idx = tid + it * 256;   // 4096: 2 planes x 64r x 32k8
        int plane = idx >> 11;
        int i2 = idx & 2047;
        int r = i2 >> 5, k8 = i2 & 31;
        const __nv_bfloat16* src = (plane ? xel : xeh) + (size_t)(row0 + r) * 256 + k8 * 8;
        CP16(sb + (plane ? N_ALO : N_AHI) + r * 528 + k8 * 16, src);
    }
    CP_COMMIT();

    // ---- preload B chunks 0,1 (k16 each: 256r x 2 k8) ----
    #pragma unroll
    for (int it = 0; it < 2; ++it) {
        int idx = tid + it * 256;   // 512
        int r = idx >> 1, k8 = idx & 1;
        CP16(sb + N_BUF + r * 48 + k8 * 16, Wb + (size_t)r * 512 + 0 * 16 + k8 * 8);
    }
    CP_COMMIT();
    #pragma unroll
    for (int it = 0; it < 2; ++it) {
        int idx = tid + it * 256;
        int r = idx >> 1, k8 = idx & 1;
        CP16(sb + N_BUF + N_BUFSZ + r * 48 + k8 * 16, Wb + (size_t)r * 512 + 1 * 16 + k8 * 8);
    }
    CP_COMMIT();

    // lane-constant offsets
    const int qi = l >> 3, ii = l & 7;
    const uint32_t b_lane = ((qi >= 2 ? 8u : 0u) + (uint32_t)ii) * 48u + (qi & 1) * 16u;
    const uint32_t a_lane = (uint32_t)(l & 15) * 528u + (uint32_t)(l >> 4) * 16u;
    const uint32_t aHiB = sb + N_AHI + m0 * 528 + a_lane;
    const uint32_t aLoB = sb + N_ALO + m0 * 528 + a_lane;
    const uint32_t bWarp = nw * 3072 + b_lane;     // nw*64 rows * 48B

    float acc[2][8][4];
    #pragma unroll
    for (int mt = 0; mt < 2; ++mt)
        #pragma unroll
        for (int nt = 0; nt < 8; ++nt)
            #pragma unroll
            for (int e = 0; e < 4; ++e) acc[mt][nt][e] = 0.f;

    // ---- mainloop: 32 k16 chunks (hi 0..15, lo 16..31) ----
    for (int cc = 0; cc < 32; ++cc) {
        if (cc < 31) { CP_WAIT1(); } else { CP_WAIT0(); }
        __syncthreads();

        if (cc + 2 < 32) {
            const int cn2 = cc + 2;
            const uint32_t dstb = sb + N_BUF + (cn2 % 3) * N_BUFSZ;
            #pragma unroll
            for (int it = 0; it < 2; ++it) {
                int idx = tid + it * 256;
                int r = idx >> 1, k8 = idx & 1;
                CP16(dstb + r * 48 + k8 * 16, Wb + (size_t)r * 512 + cn2 * 16 + k8 * 8);
            }
            CP_COMMIT();
        }

        const uint32_t bufB = sb + N_BUF + (cc % 3) * N_BUFSZ + bWarp;
        const bool hiChunk = (cc < 16);
        const uint32_t acol = (uint32_t)(cc & 15) * 32;

        uint32_t bb[8][2];
        #pragma unroll
        for (int fg = 0; fg < 4; ++fg) {
            uint32_t r0, r1, r2, r3;
            LDSM4(r0, r1, r2, r3, bufB + fg * 768);
            bb[fg * 2][0] = r0;     bb[fg * 2][1] = r1;
            bb[fg * 2 + 1][0] = r2; bb[fg * 2 + 1][1] = r3;
        }
        #pragma unroll
        for (int ap = 0; ap < 2; ++ap) {
            if (!hiChunk && ap == 1) continue;
            #pragma unroll
            for (int mt = 0; mt < 2; ++mt) {
                uint32_t a0, a1, a2, a3;
                LDSM4(a0, a1, a2, a3, (ap ? aLoB : aHiB) + mt * 8448 + acol);
                #pragma unroll
                for (int nt = 0; nt < 8; ++nt)
                    MMA_BF16(acc[mt][nt], a0, a1, a2, a3, bb[nt][0], bb[nt][1]);
            }
        }
    }

    // ---- LSTM epilogue + out reduction ----
    const float ob = (nh == 0 && nw == 0) ? __ldg(outb) : 0.f;
    const int rbase = row0 + m0 + (l >> 2);
    #pragma unroll
    for (int mt = 0; mt < 2; ++mt) {
        #pragma unroll
        for (int rh = 0; rh < 2; ++rh) {
            int R = rbase + mt * 16 + rh * 8;
            float po = 0.f;
            #pragma unroll
            for (int u = 0; u < 2; ++u) {
                int j0 = nh * 64 + nw * 16 + u * 8 + 2 * (l & 3);
                float i0 = acc[mt][u][rh * 2]          + __ldg(&bias[j0]);
                float i1 = acc[mt][u][rh * 2 + 1]      + __ldg(&bias[j0 + 1]);
                float f0 = acc[mt][2 + u][rh * 2]      + __ldg(&bias[128 + j0]);
                float f1 = acc[mt][2 + u][rh * 2 + 1]  + __ldg(&bias[128 + j0 + 1]);
                float g0 = acc[mt][4 + u][rh * 2]      + __ldg(&bias[256 + j0]);
                float g1 = acc[mt][4 + u][rh * 2 + 1]  + __ldg(&bias[256 + j0 + 1]);
                float o0 = acc[mt][6 + u][rh * 2]      + __ldg(&bias[384 + j0]);
                float o1 = acc[mt][6 + u][rh * 2 + 1]  + __ldg(&bias[384 + j0 + 1]);
                float2 cold = *(const float2*)&cn[(size_t)R * 128 + j0];
                float c0 = sigf(f0) * cold.x + sigf(i0) * tanh_f(g0);
                float c1 = sigf(f1) * cold.y + sigf(i1) * tanh_f(g1);
                float h0 = sigf(o0) * tanh_f(c0);
                float h1 = sigf(o1) * tanh_f(c1);
                *(float2*)&cn[(size_t)R * 128 + j0] = make_float2(c0, c1);
                *(float2*)&hn[(size_t)R * 128 + j0] = make_float2(h0, h1);
                po = fmaf(h0, __ldg(&outw[j0]), po);
                po = fmaf(h1, __ldg(&outw[j0 + 1]), po);
            }
            po += __shfl_xor_sync(0xffffffffu, po, 1);
            po += __shfl_xor_sync(0xffffffffu, po, 2);
            if ((l & 3) == 0) atomicAdd(&out[R], po + ob);
        }
    }
}

// ============================================================================
extern "C" void kernel_launch(void* const* d_in, const int* in_sizes, int n_in,
                              void* d_out, int out_size) {
    const float* data_nodes = (const float*)d_in[0];
    const float* data_te    = (const float*)d_in[1];
    const float* data_se    = (const float*)d_in[2];
    const float* h_n0 = (const float*)d_in[3];
    const float* c_n0 = (const float*)d_in[4];
    const float* h_t0 = (const float*)d_in[5];
    const float* c_t0 = (const float*)d_in[6];
    const float* h_s0 = (const float*)d_in[7];
    const float* c_s0 = (const float*)d_in[8];
    const int*   inc  = (const int*)d_in[9];
    const float* t_enc_w = (const float*)d_in[10];
    const float* t_enc_b = (const float*)d_in[11];
    const float* t_Wih   = (const float*)d_in[12];
    const float* t_Whh   = (const float*)d_in[13];
    const float* t_b     = (const float*)d_in[14];
    const float* s_enc_w = (const float*)d_in[15];
    const float* s_enc_b = (const float*)d_in[16];
    const float* s_Wih   = (const float*)d_in[17];
    const float* s_Whh   = (const float*)d_in[18];
    const float* s_b     = (const float*)d_in[19];
    const float* n_enc_w = (const float*)d_in[20];
    const float* n_enc_b = (const float*)d_in[21];
    const float* ee_w    = (const float*)d_in[22];
    const float* ee_b    = (const float*)d_in[23];
    const float* n_Wih   = (const float*)d_in[24];
    const float* n_Whh   = (const float*)d_in[25];
    const float* n_b     = (const float*)d_in[26];
    const float* out_w   = (const float*)d_in[27];
    const float* out_b   = (const float*)d_in[28];
    float* out = (float*)d_out;

    float *hs, *cs, *ht, *ct, *hn, *cn, *agg;
    __nv_bfloat16 *w2t_s, *w2t_t, *w2t_n, *xeh, *xel;
    cudaGetSymbolAddress((void**)&hs,  g_hs);
    cudaGetSymbolAddress((void**)&cs,  g_cs);
    cudaGetSymbolAddress((void**)&ht,  g_ht);
    cudaGetSymbolAddress((void**)&ct,  g_ct);
    cudaGetSymbolAddress((void**)&hn,  g_hn);
    cudaGetSymbolAddress((void**)&cn,  g_cn);
    cudaGetSymbolAddress((void**)&agg, g_agg);
    cudaGetSymbolAddress((void**)&w2t_s, g_w2t_s);
    cudaGetSymbolAddress((void**)&w2t_t, g_w2t_t);
    cudaGetSymbolAddress((void**)&w2t_n, g_w2t_n);
    cudaGetSymbolAddress((void**)&xeh, g_xeh);
    cudaGetSymbolAddress((void**)&xel, g_xel);

    cudaMemcpyAsync(hs, h_s0, (size_t)EE * 64  * 4, cudaMemcpyDeviceToDevice);
    cudaMemcpyAsync(cs, c_s0, (size_t)EE * 64  * 4, cudaMemcpyDeviceToDevice);
    cudaMemcpyAsync(ht, h_t0, (size_t)NN * 64  * 4, cudaMemcpyDeviceToDevice);
    cudaMemcpyAsync(ct, c_t0, (size_t)NN * 64  * 4, cudaMemcpyDeviceToDevice);
    cudaMemcpyAsync(hn, h_n0, (size_t)NN * 128 * 4, cudaMemcpyDeviceToDevice);
    cudaMemcpyAsync(cn, c_n0, (size_t)NN * 128 * 4, cudaMemcpyDeviceToDevice);
    cudaMemsetAsync(out, 0, (size_t)SSTEPS * NN * 4);

    prep_edge_w<<<128, 256>>>(s_Wih, s_Whh, w2t_s);
    prep_edge_w<<<128, 256>>>(t_Wih, t_Whh, w2t_t);
    prep_node_w<<<512, 256>>>(n_Wih, n_Whh, w2t_n);

    cudaFuncSetAttribute(edge_mma3_kernel, cudaFuncAttributeMaxDynamicSharedMemorySize, EDGE_SMEM);
    cudaFuncSetAttribute(node_mma3_kernel, cudaFuncAttributeMaxDynamicSharedMemorySize, NODE_SMEM);
    cudaFuncSetAttribute(emb_kernel,       cudaFuncAttributeMaxDynamicSharedMemorySize, EMB_SMEM);

    const int edge_grid = SE_BLOCKS + NN / 64;   // 2048 + 512
    for (int t = 0; t < SSTEPS; ++t) {
        cudaMemsetAsync(agg, 0, (size_t)NN * 64 * 4);
        edge_mma3_kernel<<<edge_grid, 256, EDGE_SMEM>>>(
            data_se + (size_t)t * EE * 2, data_te + (size_t)t * NN * 2,
            s_enc_w, s_enc_b, t_enc_w, t_enc_b,
            w2t_s, w2t_t, s_b, t_b,
            hs, cs, ht, ct, agg, inc);
        emb_kernel<<<NN / 64, 256, EMB_SMEM>>>(data_nodes + (size_t)t * NN,
                                               n_enc_w, n_enc_b, ee_w, ee_b,
                                               ht, agg, hn, xeh, xel);
        node_mma3_kernel<<<dim3(NN / 64, 2), 256, NODE_SMEM>>>(
            xeh, xel, w2t_n, n_b, out_w, out_b,
            hn, cn, out + (size_t)t * NN);
    }
}

// round 10
// speedup vs baseline: 1.8095x; 1.0119x over previous
#include <cuda_runtime.h>
#include <cuda_bf16.h>
#include <cstdint>

#define SSTEPS 16
#define NN 32768
#define EE 131072

// -------- persistent state (device globals; no allocation allowed) --------
__device__ float g_hs[(size_t)EE * 64];
__device__ float g_cs[(size_t)EE * 64];
__device__ float g_ht[(size_t)NN * 64];
__device__ float g_ct[(size_t)NN * 64];
__device__ float g_hn[(size_t)NN * 128];
__device__ float g_cn[(size_t)NN * 128];
__device__ float g_agg[(size_t)NN * 64];

// pre-split, gate-interleaved, n-major weights (bf16, k' = [hi | lo])
__device__ __nv_bfloat16 g_w2t_s[256 * 256];   // edge spatial: [rb=256][k'=256]
__device__ __nv_bfloat16 g_w2t_t[256 * 256];   // edge temporal
__device__ __nv_bfloat16 g_w2t_n[512 * 512];   // node: [rb=512][k'=512]

// node input planes: [enc(64) | emb(64) | hn_snapshot(128)] pre-split bf16
__device__ __nv_bfloat16 g_xeh[(size_t)NN * 256];
__device__ __nv_bfloat16 g_xel[(size_t)NN * 256];

__device__ __forceinline__ float sigf(float x)   { return 1.f / (1.f + __expf(-x)); }
__device__ __forceinline__ float tanh_f(float x) { return 2.f / (1.f + __expf(-2.f * x)) - 1.f; }

__device__ __forceinline__ void split_bf16(float v, __nv_bfloat16& hi, __nv_bfloat16& lo) {
    hi = __float2bfloat16(v);
    lo = __float2bfloat16(v - __bfloat162float(hi));
}

__device__ __forceinline__ void split2_store(char* baseHi, char* baseLo, uint32_t off,
                                             float v0, float v1) {
    __nv_bfloat16 h0, l0, h1, l1;
    split_bf16(v0, h0, l0);
    split_bf16(v1, h1, l1);
    *(__nv_bfloat162*)(baseHi + off) = __halves2bfloat162(h0, h1);
    *(__nv_bfloat162*)(baseLo + off) = __halves2bfloat162(l0, l1);
}

__device__ __forceinline__ uint32_t smem_u32(const void* p) {
    return (uint32_t)__cvta_generic_to_shared(p);
}

#define LDSM4(r0, r1, r2, r3, addr) \
    asm volatile("ldmatrix.sync.aligned.m8n8.x4.shared.b16 {%0,%1,%2,%3},[%4];" \
                 : "=r"(r0), "=r"(r1), "=r"(r2), "=r"(r3) : "r"(addr))

#define MMA_BF16(D, a0, a1, a2, a3, b0, b1) \
    asm volatile("mma.sync.aligned.m16n8k16.row.col.f32.bf16.bf16.f32 " \
                 "{%0,%1,%2,%3},{%4,%5,%6,%7},{%8,%9},{%0,%1,%2,%3};" \
                 : "+f"(D[0]), "+f"(D[1]), "+f"(D[2]), "+f"(D[3]) \
                 : "r"(a0), "r"(a1), "r"(a2), "r"(a3), "r"(b0), "r"(b1))

#define CP16(saddr, gptr) \
    asm volatile("cp.async.cg.shared.global [%0],[%1],16;" :: "r"(saddr), "l"(gptr))
#define CP_COMMIT() asm volatile("cp.async.commit_group;")
#define CP_WAIT0()  asm volatile("cp.async.wait_group 0;")
#define CP_WAIT1()  asm volatile("cp.async.wait_group 1;")

// vector reduction to global (sm_90+): 4 floats, one instruction
#define RED4(ptr, v) \
    asm volatile("red.global.add.v4.f32 [%0], {%1,%2,%3,%4};" \
                 :: "l"(ptr), "f"((v).x), "f"((v).y), "f"((v).z), "f"((v).w) : "memory")

// ============================================================================
// weight prep (gate-interleaved for 4 N-warps of n64)
// edge rb = nw*64 + g*16 + jj  -> orig_n = g*64 + nw*16 + jj
// ============================================================================
__global__ void prep_edge_w(const float* __restrict__ Wih, const float* __restrict__ Whh,
                            __nv_bfloat16* __restrict__ W2t) {
    int idx = blockIdx.x * 256 + threadIdx.x;   // 256 rb * 128 k
    int rb = idx >> 7, k = idx & 127;
    int nw = rb >> 6, g = (rb >> 4) & 3, jj = rb & 15;
    int orig_n = g * 64 + nw * 16 + jj;
    float v = (k < 64) ? Wih[k * 256 + orig_n] : Whh[(k - 64) * 256 + orig_n];
    __nv_bfloat16 hi, lo; split_bf16(v, hi, lo);
    W2t[rb * 256 + k] = hi;
    W2t[rb * 256 + 128 + k] = lo;
}

// node rb = nh*256 + nw*64 + g*16 + jj -> orig_n = g*128 + nh*64 + nw*16 + jj
__global__ void prep_node_w(const float* __restrict__ Wih, const float* __restrict__ Whh,
                            __nv_bfloat16* __restrict__ W2t) {
    int idx = blockIdx.x * 256 + threadIdx.x;   // 512 rb * 256 k
    int rb = idx >> 8, k = idx & 255;
    int nh = rb >> 8, nw = (rb >> 6) & 3, g = (rb >> 4) & 3, jj = rb & 15;
    int orig_n = g * 128 + nh * 64 + nw * 16 + jj;
    float v = (k < 128) ? Wih[k * 512 + orig_n] : Whh[(k - 128) * 512 + orig_n];
    __nv_bfloat16 hi, lo; split_bf16(v, hi, lo);
    W2t[rb * 512 + k] = hi;
    W2t[rb * 512 + 256 + k] = lo;
}

// ============================================================================
// Edge LSTM (hidden 64, K=128, N=256), merged spatial+temporal.
// Block = 64 rows, 8 warps (2M x 4N), warp tile m32 x n64, 2 blocks/SM.
// SMEM: Ahi [64][136]bf16 17408 | Alo 17408 | Cs_in [64][68]f32 17408 |
//       inc 512 | 3x Bbuf [256][40bf16] 20480
// After mainloop, A region reused as Hs/Cs_out [64 rows x 272B] f32 staging.
// ============================================================================
#define E_AHI 0
#define E_ALO 17408
#define E_CS  34816
#define E_INC 52224
#define E_BUF 52736
#define E_BUFSZ 20480
#define EDGE_SMEM (52736 + 3 * 20480)
#define SE_BLOCKS (EE / 64)

__global__ __launch_bounds__(256, 2) void edge_mma4_kernel(
    const float* __restrict__ x_s, const float* __restrict__ x_t,
    const float* __restrict__ encw_s, const float* __restrict__ encb_s,
    const float* __restrict__ encw_t, const float* __restrict__ encb_t,
    const __nv_bfloat16* __restrict__ W2t_s, const __nv_bfloat16* __restrict__ W2t_t,
    const float* __restrict__ bias_s, const float* __restrict__ bias_t,
    float* __restrict__ h_s, float* __restrict__ c_s,
    float* __restrict__ h_t, float* __restrict__ c_t,
    float* __restrict__ agg, const int* __restrict__ inc)
{
    extern __shared__ char sm[];
    const uint32_t sb = smem_u32(sm);
    const int tid = threadIdx.x;
    const int wid = tid >> 5, l = tid & 31;
    const int mw = wid & 1, nw = wid >> 1;
    const int m0 = mw * 32;

    const bool is_se = (blockIdx.x < SE_BLOCKS);
    const int row0 = (is_se ? blockIdx.x : (blockIdx.x - SE_BLOCKS)) * 64;
    const float* x    = is_se ? x_s : x_t;
    const float* encw = is_se ? encw_s : encw_t;
    const float* encb = is_se ? encb_s : encb_t;
    const __nv_bfloat16* W2t = is_se ? W2t_s : W2t_t;
    const float* bias = is_se ? bias_s : bias_t;
    float* h = is_se ? h_s : h_t;
    float* c = is_se ? c_s : c_t;
    float* aggp = is_se ? agg : nullptr;

    // ---- group 0: B chunk0 + Cs_in (c tile) + inc ----
    #pragma unroll
    for (int it = 0; it < 4; ++it) {
        int idx = tid + it * 256;                 // 1024 = 256r x 4k8
        int r = idx >> 2, k8 = idx & 3;
        CP16(sb + E_BUF + r * 80 + k8 * 16, W2t + (size_t)r * 256 + 0 * 32 + k8 * 8);
    }
    #pragma unroll
    for (int it = 0; it < 4; ++it) {
        int idx = tid + it * 256;                 // 1024 = 64r x 16 seg
        int r = idx >> 4, seg = idx & 15;
        CP16(sb + E_CS + r * 272 + seg * 16, c + (size_t)(row0 + r) * 64 + seg * 4);
    }
    if (is_se && tid < 32)
        CP16(sb + E_INC + tid * 16, inc + 2 * row0 + tid * 4);
    CP_COMMIT();
    // ---- group 1: B chunk1 ----
    #pragma unroll
    for (int it = 0; it < 4; ++it) {
        int idx = tid + it * 256;
        int r = idx >> 2, k8 = idx & 3;
        CP16(sb + E_BUF + E_BUFSZ + r * 80 + k8 * 16, W2t + (size_t)r * 256 + 1 * 32 + k8 * 8);
    }
    CP_COMMIT();

    // ---- stage A (enc cols 0..63, h cols 64..127), split planes ----
    #pragma unroll
    for (int it = 0; it < 8; ++it) {
        int idx = tid + it * 256;                 // 2048 = 64r x 32 j4-groups
        int r = idx >> 5, j4 = idx & 31;
        int R = row0 + r;
        if (j4 < 16) {
            float x0 = x[R * 2 + 0], x1 = x[R * 2 + 1];
            int j = j4 * 4;
            #pragma unroll
            for (int e = 0; e < 2; ++e) {
                int cc = j + e * 2;
                float v0 = fmaxf(fmaf(x0, __ldg(&encw[cc]),     fmaf(x1, __ldg(&encw[64 + cc]),     __ldg(&encb[cc]))), 0.f);
                float v1 = fmaxf(fmaf(x0, __ldg(&encw[cc + 1]), fmaf(x1, __ldg(&encw[64 + cc + 1]), __ldg(&encb[cc + 1]))), 0.f);
                split2_store(sm + E_AHI, sm + E_ALO, r * 272 + cc * 2, v0, v1);
            }
        } else {
            int j = (j4 - 16) * 4;
            float4 hv = *(const float4*)&h[(size_t)R * 64 + j];
            split2_store(sm + E_AHI, sm + E_ALO, r * 272 + (64 + j) * 2, hv.x, hv.y);
            split2_store(sm + E_AHI, sm + E_ALO, r * 272 + (64 + j + 2) * 2, hv.z, hv.w);
        }
    }

    // ---- lane-constant offsets ----
    const int qi = l >> 3, ii = l & 7;
    const uint32_t b_lane = ((qi >= 2 ? 8u : 0u) + (uint32_t)ii) * 80u + (qi & 1) * 16u;
    const uint32_t a_lane = (uint32_t)(l & 15) * 272u + (uint32_t)(l >> 4) * 16u;
    const uint32_t aHiB = sb + E_AHI + m0 * 272 + a_lane;
    const uint32_t aLoB = sb + E_ALO + m0 * 272 + a_lane;
    const uint32_t bWarp = nw * 5120 + b_lane;      // nw*64 rows * 80B

    float acc[2][8][4];
    #pragma unroll
    for (int mt = 0; mt < 2; ++mt)
        #pragma unroll
        for (int nt = 0; nt < 8; ++nt)
            #pragma unroll
            for (int e = 0; e < 4; ++e) acc[mt][nt][e] = 0.f;

    // ---- mainloop: 8 k32 chunks (hi 0..3, lo 4..7) ----
    for (int cc = 0; cc < 8; ++cc) {
        if (cc < 7) { CP_WAIT1(); } else { CP_WAIT0(); }
        __syncthreads();

        if (cc + 2 < 8) {
            const int cn2 = cc + 2;
            const uint32_t dstb = sb + E_BUF + (cn2 % 3) * E_BUFSZ;
            #pragma unroll
            for (int it = 0; it < 4; ++it) {
                int idx = tid + it * 256;
                int r = idx >> 2, k8 = idx & 3;
                CP16(dstb + r * 80 + k8 * 16, W2t + (size_t)r * 256 + cn2 * 32 + k8 * 8);
            }
            CP_COMMIT();
        }

        const uint32_t bufB = sb + E_BUF + (cc % 3) * E_BUFSZ + bWarp;
        const bool hiChunk = (cc < 4);
        const uint32_t acol = (uint32_t)(cc & 3) * 64;

        #pragma unroll
        for (int ks2 = 0; ks2 < 2; ++ks2) {
            uint32_t bb[8][2];
            #pragma unroll
            for (int fg = 0; fg < 4; ++fg) {
                uint32_t r0, r1, r2, r3;
                LDSM4(r0, r1, r2, r3, bufB + fg * 1280 + ks2 * 32);
                bb[fg * 2][0] = r0;     bb[fg * 2][1] = r1;
                bb[fg * 2 + 1][0] = r2; bb[fg * 2 + 1][1] = r3;
            }
            #pragma unroll
            for (int ap = 0; ap < 2; ++ap) {
                if (!hiChunk && ap == 1) continue;
                #pragma unroll
                for (int mt = 0; mt < 2; ++mt) {
                    uint32_t a0, a1, a2, a3;
                    LDSM4(a0, a1, a2, a3, (ap ? aLoB : aHiB) + mt * 4352 + acol + ks2 * 32);
                    #pragma unroll
                    for (int nt = 0; nt < 8; ++nt)
                        MMA_BF16(acc[mt][nt], a0, a1, a2, a3, bb[nt][0], bb[nt][1]);
                }
            }
        }
    }

    // ---- epilogue: gates -> staged h/c in reused A region (272B stride) ----
    __syncthreads();   // all warps done with A planes / B bufs

    const int rl_base = m0 + (l >> 2);
    #pragma unroll
    for (int mt = 0; mt < 2; ++mt) {
        #pragma unroll
        for (int rh = 0; rh < 2; ++rh) {
            int rl = rl_base + mt * 16 + rh * 8;
            #pragma unroll
            for (int u = 0; u < 2; ++u) {
                int j0 = nw * 16 + u * 8 + 2 * (l & 3);
                float i0 = acc[mt][u][rh * 2]          + __ldg(&bias[j0]);
                float i1 = acc[mt][u][rh * 2 + 1]      + __ldg(&bias[j0 + 1]);
                float f0 = acc[mt][2 + u][rh * 2]      + __ldg(&bias[64 + j0]);
                float f1 = acc[mt][2 + u][rh * 2 + 1]  + __ldg(&bias[64 + j0 + 1]);
                float g0 = acc[mt][4 + u][rh * 2]      + __ldg(&bias[128 + j0]);
                float g1 = acc[mt][4 + u][rh * 2 + 1]  + __ldg(&bias[128 + j0 + 1]);
                float o0 = acc[mt][6 + u][rh * 2]      + __ldg(&bias[192 + j0]);
                float o1 = acc[mt][6 + u][rh * 2 + 1]  + __ldg(&bias[192 + j0 + 1]);
                float2 cold = *(const float2*)(sm + E_CS + rl * 272 + j0 * 4);
                float c0 = sigf(f0) * cold.x + sigf(i0) * tanh_f(g0);
                float c1 = sigf(f1) * cold.y + sigf(i1) * tanh_f(g1);
                float h0 = sigf(o0) * tanh_f(c0);
                float h1 = sigf(o1) * tanh_f(c1);
                *(float2*)(sm + rl * 272 + j0 * 4)         = make_float2(h0, h1);
                *(float2*)(sm + 17408 + rl * 272 + j0 * 4) = make_float2(c0, c1);
            }
        }
    }
    __syncthreads();

    // ---- cooperative coalesced writeback + vector red scatter ----
    const int* incs = (const int*)(sm + E_INC);
    #pragma unroll
    for (int p = 0; p < 4; ++p) {
        int r = p * 16 + (tid >> 4);
        int j4 = tid & 15;
        int R = row0 + r;
        float4 hv = *(const float4*)(sm + r * 272 + j4 * 16);
        float4 cv = *(const float4*)(sm + 17408 + r * 272 + j4 * 16);
        *(float4*)&h[(size_t)R * 64 + j4 * 4] = hv;
        *(float4*)&c[(size_t)R * 64 + j4 * 4] = cv;
        if (aggp) {
            int n0 = incs[2 * r], n1 = incs[2 * r + 1];
            RED4(&aggp[(size_t)n0 * 64 + j4 * 4], hv);
            RED4(&aggp[(size_t)n1 * 64 + j4 * 4], hv);
        }
    }
}

// ============================================================================
// emb kernel: enc/emb + hn snapshot into planes (unchanged).
// ============================================================================
#define EMB_SMEM (64 * 132 * 4 + 128 * 64 * 4)

__global__ __launch_bounds__(256) void emb_kernel(
    const float* __restrict__ xn,
    const float* __restrict__ nencw, const float* __restrict__ nencb,
    const float* __restrict__ eew,   const float* __restrict__ eeb,
    const float* __restrict__ ht,    const float* __restrict__ agg,
    const float* __restrict__ hn,
    __nv_bfloat16* __restrict__ xeh, __nv_bfloat16* __restrict__ xel)
{
    extern __shared__ float smf[];
    float* Asf  = smf;                 // [64][132]
    float* eewS = smf + 64 * 132;      // [128][64]

    const int tid = threadIdx.x;
    const int row0 = blockIdx.x * 64;

    #pragma unroll
    for (int it = 0; it < 16; ++it) {
        int idx = tid + it * 256;
        int r = idx >> 6, j = idx & 63;
        int R = row0 + r;
        Asf[r * 132 + j]      = ht[(size_t)R * 64 + j];
        Asf[r * 132 + 64 + j] = agg[(size_t)R * 64 + j];
    }
    #pragma unroll
    for (int it = 0; it < 8; ++it) {
        int f4 = tid + it * 256;
        *(float4*)&eewS[f4 * 4] = *(const float4*)&eew[f4 * 4];
    }

    #pragma unroll
    for (int it = 0; it < 16; ++it) {
        int idx = tid + it * 256;
        int r = idx >> 6, jp = idx & 63;
        int R = row0 + r;
        float2 hv = *(const float2*)&hn[(size_t)R * 128 + jp * 2];
        split2_store((char*)(xeh + (size_t)R * 256), (char*)(xel + (size_t)R * 256),
                     (128 + jp * 2) * 2, hv.x, hv.y);
    }
    __syncthreads();

    const int r = tid >> 2, jq = tid & 3;
    const int R = row0 + r;

    {
        float xv = xn[R];
        #pragma unroll
        for (int u = 0; u < 8; ++u) {
            int cc = jq * 16 + u * 2;
            float v0 = fmaxf(fmaf(xv, __ldg(&nencw[cc]),     __ldg(&nencb[cc])), 0.f);
            float v1 = fmaxf(fmaf(xv, __ldg(&nencw[cc + 1]), __ldg(&nencb[cc + 1])), 0.f);
            split2_store((char*)(xeh + (size_t)R * 256), (char*)(xel + (size_t)R * 256),
                         cc * 2, v0, v1);
        }
    }

    {
        float accv[16];
        #pragma unroll
        for (int u = 0; u < 16; ++u) accv[u] = __ldg(&eeb[jq * 16 + u]);
        #pragma unroll 4
        for (int k = 0; k < 128; ++k) {
            float a = Asf[r * 132 + k];
            #pragma unroll
            for (int g = 0; g < 4; ++g) {
                float4 w4 = *(const float4*)&eewS[k * 64 + jq * 16 + g * 4];
                accv[g*4+0] = fmaf(a, w4.x, accv[g*4+0]);
                accv[g*4+1] = fmaf(a, w4.y, accv[g*4+1]);
                accv[g*4+2] = fmaf(a, w4.z, accv[g*4+2]);
                accv[g*4+3] = fmaf(a, w4.w, accv[g*4+3]);
            }
        }
        #pragma unroll
        for (int u = 0; u < 8; ++u) {
            float v0 = fmaxf(accv[u * 2], 0.f);
            float v1 = fmaxf(accv[u * 2 + 1], 0.f);
            int cc = 64 + jq * 16 + u * 2;
            split2_store((char*)(xeh + (size_t)R * 256), (char*)(xel + (size_t)R * 256),
                         cc * 2, v0, v1);
        }
    }
}

// ============================================================================
// Node LSTM GEMM (hidden 128, K=256). Grid (NN/64, 2); block = 64 rows,
// N-half. 8 warps 2M x 4N, warp tile m32 x n64, 2 blocks/SM.
// cn cold prefetched to REGISTERS before mainloop; epilogue staged in
// reused A SMEM (272B stride, 16-aligned) for coalesced writeback.
// SMEM: Ahi [64][264] 33792 | Alo 33792 | 3x Bbuf [256][24] 12288
// ============================================================================
#define N_AHI 0
#define N_ALO 33792
#define N_BUF 67584
#define N_BUFSZ 12288
#define NODE_SMEM (67584 + 3 * 12288)

__global__ __launch_bounds__(256, 2) void node_mma4_kernel(
    const __nv_bfloat16* __restrict__ xeh, const __nv_bfloat16* __restrict__ xel,
    const __nv_bfloat16* __restrict__ W2t,
    const float* __restrict__ bias,
    const float* __restrict__ outw,  const float* __restrict__ outb,
    float* __restrict__ hn, float* __restrict__ cn,
    float* __restrict__ out)
{
    extern __shared__ char sm[];
    const uint32_t sb = smem_u32(sm);
    const int tid = threadIdx.x;
    const int wid = tid >> 5, l = tid & 31;
    const int mw = wid & 1, nw = wid >> 1;
    const int m0 = mw * 32;
    const int row0 = blockIdx.x * 64;
    const int nh = blockIdx.y;
    const __nv_bfloat16* Wb = W2t + (size_t)(nh * 256) * 512;

    // ---- group 0: stage A (256 cols from pre-split planes) ----
    #pragma unroll
    for (int it = 0; it < 16; ++it) {
        int idx = tid + it * 256;   // 4096: 2 planes x 64r x 32k8
        int plane = idx >> 11;
        int i2 = idx & 2047;
        int r = i2 >> 5, k8 = i2 & 31;
        const __nv_bfloat16* src = (plane ? xel : xeh) + (size_t)(row0 + r) * 256 + k8 * 8;
        CP16(sb + (plane ? N_ALO : N_AHI) + r * 528 + k8 * 16, src);
    }
    CP_COMMIT();

    // ---- groups 1,2: preload B chunks 0,1 (k16 each) ----
    #pragma unroll
    for (int it = 0; it < 2; ++it) {
        int idx = tid + it * 256;
        int r = idx >> 1, k8 = idx & 1;
        CP16(sb + N_BUF + r * 48 + k8 * 16, Wb + (size_t)r * 512 + 0 * 16 + k8 * 8);
    }
    CP_COMMIT();
    #pragma unroll
    for (int it = 0; it < 2; ++it) {
        int idx = tid + it * 256;
        int r = idx >> 1, k8 = idx & 1;
        CP16(sb + N_BUF + N_BUFSZ + r * 48 + k8 * 16, Wb + (size_t)r * 512 + 1 * 16 + k8 * 8);
    }
    CP_COMMIT();

    // ---- cold (cn) register prefetch: latency hidden by mainloop ----
    float2 cold[2][2][2];
    #pragma unroll
    for (int mt = 0; mt < 2; ++mt)
        #pragma unroll
        for (int rh = 0; rh < 2; ++rh)
            #pragma unroll
            for (int u = 0; u < 2; ++u) {
                int R = row0 + m0 + (l >> 2) + mt * 16 + rh * 8;
                int j0 = nh * 64 + nw * 16 + u * 8 + 2 * (l & 3);
                cold[mt][rh][u] = __ldg((const float2*)&cn[(size_t)R * 128 + j0]);
            }

    // lane-constant offsets
    const int qi = l >> 3, ii = l & 7;
    const uint32_t b_lane = ((qi >= 2 ? 8u : 0u) + (uint32_t)ii) * 48u + (qi & 1) * 16u;
    const uint32_t a_lane = (uint32_t)(l & 15) * 528u + (uint32_t)(l >> 4) * 16u;
    const uint32_t aHiB = sb + N_AHI + m0 * 528 + a_lane;
    const uint32_t aLoB = sb + N_ALO + m0 * 528 + a_lane;
    const uint32_t bWarp = nw * 3072 + b_lane;

    float acc[2][8][4];
    #pragma unroll
    for (int mt = 0; mt < 2; ++mt)
        #pragma unroll
        for (int nt = 0; nt < 8; ++nt)
            #pragma unroll
            for (int e = 0; e < 4; ++e) acc[mt][nt][e] = 0.f;

    // ---- mainloop: 32 k16 chunks (hi 0..15, lo 16..31) ----
    for (int cc = 0; cc < 32; ++cc) {
        if (cc < 31) { CP_WAIT1(); } else { CP_WAIT0(); }
        __syncthreads();

        if (cc + 2 < 32) {
            const int cn2 = cc + 2;
            const uint32_t dstb = sb + N_BUF + (cn2 % 3) * N_BUFSZ;
            #pragma unroll
            for (int it = 0; it < 2; ++it) {
                int idx = tid + it * 256;
                int r = idx >> 1, k8 = idx & 1;
                CP16(dstb + r * 48 + k8 * 16, Wb + (size_t)r * 512 + cn2 * 16 + k8 * 8);
            }
            CP_COMMIT();
        }

        const uint32_t bufB = sb + N_BUF + (cc % 3) * N_BUFSZ + bWarp;
        const bool hiChunk = (cc < 16);
        const uint32_t acol = (uint32_t)(cc & 15) * 32;

        uint32_t bb[8][2];
        #pragma unroll
        for (int fg = 0; fg < 4; ++fg) {
            uint32_t r0, r1, r2, r3;
            LDSM4(r0, r1, r2, r3, bufB + fg * 768);
            bb[fg * 2][0] = r0;     bb[fg * 2][1] = r1;
            bb[fg * 2 + 1][0] = r2; bb[fg * 2 + 1][1] = r3;
        }
        #pragma unroll
        for (int ap = 0; ap < 2; ++ap) {
            if (!hiChunk && ap == 1) continue;
            #pragma unroll
            for (int mt = 0; mt < 2; ++mt) {
                uint32_t a0, a1, a2, a3;
                LDSM4(a0, a1, a2, a3, (ap ? aLoB : aHiB) + mt * 8448 + acol);
                #pragma unroll
                for (int nt = 0; nt < 8; ++nt)
                    MMA_BF16(acc[mt][nt], a0, a1, a2, a3, bb[nt][0], bb[nt][1]);
            }
        }
    }

    // ---- epilogue: gates -> staged h/c (272B stride, 16-aligned) ----
    __syncthreads();

    const float ob = (nh == 0 && nw == 0) ? __ldg(outb) : 0.f;
    const int rl_base = m0 + (l >> 2);
    #pragma unroll
    for (int mt = 0; mt < 2; ++mt) {
        #pragma unroll
        for (int rh = 0; rh < 2; ++rh) {
            int rl = rl_base + mt * 16 + rh * 8;
            int R = row0 + rl;
            float po = 0.f;
            #pragma unroll
            for (int u = 0; u < 2; ++u) {
                int j0 = nh * 64 + nw * 16 + u * 8 + 2 * (l & 3);
                int jl = j0 - nh * 64;
                float i0 = acc[mt][u][rh * 2]          + __ldg(&bias[j0]);
                float i1 = acc[mt][u][rh * 2 + 1]      + __ldg(&bias[j0 + 1]);
                float f0 = acc[mt][2 + u][rh * 2]      + __ldg(&bias[128 + j0]);
                float f1 = acc[mt][2 + u][rh * 2 + 1]  + __ldg(&bias[128 + j0 + 1]);
                float g0 = acc[mt][4 + u][rh * 2]      + __ldg(&bias[256 + j0]);
                float g1 = acc[mt][4 + u][rh * 2 + 1]  + __ldg(&bias[256 + j0 + 1]);
                float o0 = acc[mt][6 + u][rh * 2]      + __ldg(&bias[384 + j0]);
                float o1 = acc[mt][6 + u][rh * 2 + 1]  + __ldg(&bias[384 + j0 + 1]);
                float2 cv = cold[mt][rh][u];
                float c0 = sigf(f0) * cv.x + sigf(i0) * tanh_f(g0);
                float c1 = sigf(f1) * cv.y + sigf(i1) * tanh_f(g1);
                float h0 = sigf(o0) * tanh_f(c0);
                float h1 = sigf(o1) * tanh_f(c1);
                *(float2*)(sm + rl * 272 + jl * 4)         = make_float2(h0, h1);
                *(float2*)(sm + 17408 + rl * 272 + jl * 4) = make_float2(c0, c1);
                po = fmaf(h0, __ldg(&outw[j0]), po);
                po = fmaf(h1, __ldg(&outw[j0 + 1]), po);
            }
            po += __shfl_xor_sync(0xffffffffu, po, 1);
            po += __shfl_xor_sync(0xffffffffu, po, 2);
            if ((l & 3) == 0) atomicAdd(&out[R], po + ob);
        }
    }
    __syncthreads();

    // ---- cooperative coalesced writeback (64 cols per block) ----
    #pragma unroll
    for (int p = 0; p < 4; ++p) {
        int r = p * 16 + (tid >> 4);
        int j4 = tid & 15;
        int R = row0 + r;
        float4 hv = *(const float4*)(sm + r * 272 + j4 * 16);
        float4 cv = *(const float4*)(sm + 17408 + r * 272 + j4 * 16);
        *(float4*)&hn[(size_t)R * 128 + nh * 64 + j4 * 4] = hv;
        *(float4*)&cn[(size_t)R * 128 + nh * 64 + j4 * 4] = cv;
    }
}

// ============================================================================
extern "C" void kernel_launch(void* const* d_in, const int* in_sizes, int n_in,
                              void* d_out, int out_size) {
    const float* data_nodes = (const float*)d_in[0];
    const float* data_te    = (const float*)d_in[1];
    const float* data_se    = (const float*)d_in[2];
    const float* h_n0 = (const float*)d_in[3];
    const float* c_n0 = (const float*)d_in[4];
    const float* h_t0 = (const float*)d_in[5];
    const float* c_t0 = (const float*)d_in[6];
    const float* h_s0 = (const float*)d_in[7];
    const float* c_s0 = (const float*)d_in[8];
    const int*   inc  = (const int*)d_in[9];
    const float* t_enc_w = (const float*)d_in[10];
    const float* t_enc_b = (const float*)d_in[11];
    const float* t_Wih   = (const float*)d_in[12];
    const float* t_Whh   = (const float*)d_in[13];
    const float* t_b     = (const float*)d_in[14];
    const float* s_enc_w = (const float*)d_in[15];
    const float* s_enc_b = (const float*)d_in[16];
    const float* s_Wih   = (const float*)d_in[17];
    const float* s_Whh   = (const float*)d_in[18];
    const float* s_b     = (const float*)d_in[19];
    const float* n_enc_w = (const float*)d_in[20];
    const float* n_enc_b = (const float*)d_in[21];
    const float* ee_w    = (const float*)d_in[22];
    const float* ee_b    = (const float*)d_in[23];
    const float* n_Wih   = (const float*)d_in[24];
    const float* n_Whh   = (const float*)d_in[25];
    const float* n_b     = (const float*)d_in[26];
    const float* out_w   = (const float*)d_in[27];
    const float* out_b   = (const float*)d_in[28];
    float* out = (float*)d_out;

    float *hs, *cs, *ht, *ct, *hn, *cn, *agg;
    __nv_bfloat16 *w2t_s, *w2t_t, *w2t_n, *xeh, *xel;
    cudaGetSymbolAddress((void**)&hs,  g_hs);
    cudaGetSymbolAddress((void**)&cs,  g_cs);
    cudaGetSymbolAddress((void**)&ht,  g_ht);
    cudaGetSymbolAddress((void**)&ct,  g_ct);
    cudaGetSymbolAddress((void**)&hn,  g_hn);
    cudaGetSymbolAddress((void**)&cn,  g_cn);
    cudaGetSymbolAddress((void**)&agg, g_agg);
    cudaGetSymbolAddress((void**)&w2t_s, g_w2t_s);
    cudaGetSymbolAddress((void**)&w2t_t, g_w2t_t);
    cudaGetSymbolAddress((void**)&w2t_n, g_w2t_n);
    cudaGetSymbolAddress((void**)&xeh, g_xeh);
    cudaGetSymbolAddress((void**)&xel, g_xel);

    cudaMemcpyAsync(hs, h_s0, (size_t)EE * 64  * 4, cudaMemcpyDeviceToDevice);
    cudaMemcpyAsync(cs, c_s0, (size_t)EE * 64  * 4, cudaMemcpyDeviceToDevice);
    cudaMemcpyAsync(ht, h_t0, (size_t)NN * 64  * 4, cudaMemcpyDeviceToDevice);
    cudaMemcpyAsync(ct, c_t0, (size_t)NN * 64  * 4, cudaMemcpyDeviceToDevice);
    cudaMemcpyAsync(hn, h_n0, (size_t)NN * 128 * 4, cudaMemcpyDeviceToDevice);
    cudaMemcpyAsync(cn, c_n0, (size_t)NN * 128 * 4, cudaMemcpyDeviceToDevice);
    cudaMemsetAsync(out, 0, (size_t)SSTEPS * NN * 4);

    prep_edge_w<<<128, 256>>>(s_Wih, s_Whh, w2t_s);
    prep_edge_w<<<128, 256>>>(t_Wih, t_Whh, w2t_t);
    prep_node_w<<<512, 256>>>(n_Wih, n_Whh, w2t_n);

    cudaFuncSetAttribute(edge_mma4_kernel, cudaFuncAttributeMaxDynamicSharedMemorySize, EDGE_SMEM);
    cudaFuncSetAttribute(node_mma4_kernel, cudaFuncAttributeMaxDynamicSharedMemorySize, NODE_SMEM);
    cudaFuncSetAttribute(emb_kernel,       cudaFuncAttributeMaxDynamicSharedMemorySize, EMB_SMEM);

    const int edge_grid = SE_BLOCKS + NN / 64;   // 2048 + 512
    for (int t = 0; t < SSTEPS; ++t) {
        cudaMemsetAsync(agg, 0, (size_t)NN * 64 * 4);
        edge_mma4_kernel<<<edge_grid, 256, EDGE_SMEM>>>(
            data_se + (size_t)t * EE * 2, data_te + (size_t)t * NN * 2,
            s_enc_w, s_enc_b, t_enc_w, t_enc_b,
            w2t_s, w2t_t, s_b, t_b,
            hs, cs, ht, ct, agg, inc);
        emb_kernel<<<NN / 64, 256, EMB_SMEM>>>(data_nodes + (size_t)t * NN,
                                               n_enc_w, n_enc_b, ee_w, ee_b,
                                               ht, agg, hn, xeh, xel);
        node_mma4_kernel<<<dim3(NN / 64, 2), 256, NODE_SMEM>>>(
            xeh, xel, w2t_n, n_b, out_w, out_b,
            hn, cn, out + (size_t)t * NN);
    }
}

// round 11
// speedup vs baseline: 1.9705x; 1.0890x over previous
#include <cuda_runtime.h>
#include <cuda_bf16.h>
#include <cstdint>

#define SSTEPS 16
#define NN 32768
#define EE 131072

// -------- persistent state (device globals; no allocation allowed) --------
__device__ float g_hs[(size_t)EE * 64];
__device__ float g_cs[(size_t)EE * 64];
__device__ float g_ht3[(size_t)3 * NN * 64];   // triple-buffered temporal h
__device__ float g_ct[(size_t)NN * 64];
__device__ float g_hn[(size_t)NN * 128];
__device__ float g_cn[(size_t)NN * 128];
__device__ float g_agg2[(size_t)2 * NN * 64];  // double-buffered agg

// pre-split, gate-interleaved, n-major weights (bf16, k' = [hi | lo])
__device__ __nv_bfloat16 g_w2t_s[256 * 256];
__device__ __nv_bfloat16 g_w2t_t[256 * 256];
__device__ __nv_bfloat16 g_w2t_n[512 * 512];

// node input planes: [enc(64) | emb(64) | hn_snapshot(128)] pre-split bf16
__device__ __nv_bfloat16 g_xeh[(size_t)NN * 256];
__device__ __nv_bfloat16 g_xel[(size_t)NN * 256];

__device__ __forceinline__ float sigf(float x)   { return 1.f / (1.f + __expf(-x)); }
__device__ __forceinline__ float tanh_f(float x) { return 2.f / (1.f + __expf(-2.f * x)) - 1.f; }

__device__ __forceinline__ void split_bf16(float v, __nv_bfloat16& hi, __nv_bfloat16& lo) {
    hi = __float2bfloat16(v);
    lo = __float2bfloat16(v - __bfloat162float(hi));
}

__device__ __forceinline__ void split2_store(char* baseHi, char* baseLo, uint32_t off,
                                             float v0, float v1) {
    __nv_bfloat16 h0, l0, h1, l1;
    split_bf16(v0, h0, l0);
    split_bf16(v1, h1, l1);
    *(__nv_bfloat162*)(baseHi + off) = __halves2bfloat162(h0, h1);
    *(__nv_bfloat162*)(baseLo + off) = __halves2bfloat162(l0, l1);
}

__device__ __forceinline__ uint32_t smem_u32(const void* p) {
    return (uint32_t)__cvta_generic_to_shared(p);
}

#define LDSM4(r0, r1, r2, r3, addr) \
    asm volatile("ldmatrix.sync.aligned.m8n8.x4.shared.b16 {%0,%1,%2,%3},[%4];" \
                 : "=r"(r0), "=r"(r1), "=r"(r2), "=r"(r3) : "r"(addr))

#define MMA_BF16(D, a0, a1, a2, a3, b0, b1) \
    asm volatile("mma.sync.aligned.m16n8k16.row.col.f32.bf16.bf16.f32 " \
                 "{%0,%1,%2,%3},{%4,%5,%6,%7},{%8,%9},{%0,%1,%2,%3};" \
                 : "+f"(D[0]), "+f"(D[1]), "+f"(D[2]), "+f"(D[3]) \
                 : "r"(a0), "r"(a1), "r"(a2), "r"(a3), "r"(b0), "r"(b1))

#define CP16(saddr, gptr) \
    asm volatile("cp.async.cg.shared.global [%0],[%1],16;" :: "r"(saddr), "l"(gptr))
#define CP_COMMIT() asm volatile("cp.async.commit_group;")
#define CP_WAIT0()  asm volatile("cp.async.wait_group 0;")
#define CP_WAIT1()  asm volatile("cp.async.wait_group 1;")

#define RED4(ptr, v) \
    asm volatile("red.global.add.v4.f32 [%0], {%1,%2,%3,%4};" \
                 :: "l"(ptr), "f"((v).x), "f"((v).y), "f"((v).z), "f"((v).w) : "memory")

// ============================================================================
// weight prep (gate-interleaved for 4 N-warps of n64)
// ============================================================================
__global__ void prep_edge_w(const float* __restrict__ Wih, const float* __restrict__ Whh,
                            __nv_bfloat16* __restrict__ W2t) {
    int idx = blockIdx.x * 256 + threadIdx.x;
    int rb = idx >> 7, k = idx & 127;
    int nw = rb >> 6, g = (rb >> 4) & 3, jj = rb & 15;
    int orig_n = g * 64 + nw * 16 + jj;
    float v = (k < 64) ? Wih[k * 256 + orig_n] : Whh[(k - 64) * 256 + orig_n];
    __nv_bfloat16 hi, lo; split_bf16(v, hi, lo);
    W2t[rb * 256 + k] = hi;
    W2t[rb * 256 + 128 + k] = lo;
}

__global__ void prep_node_w(const float* __restrict__ Wih, const float* __restrict__ Whh,
                            __nv_bfloat16* __restrict__ W2t) {
    int idx = blockIdx.x * 256 + threadIdx.x;
    int rb = idx >> 8, k = idx & 255;
    int nh = rb >> 8, nw = (rb >> 6) & 3, g = (rb >> 4) & 3, jj = rb & 15;
    int orig_n = g * 128 + nh * 64 + nw * 16 + jj;
    float v = (k < 128) ? Wih[k * 512 + orig_n] : Whh[(k - 128) * 512 + orig_n];
    __nv_bfloat16 hi, lo; split_bf16(v, hi, lo);
    W2t[rb * 512 + k] = hi;
    W2t[rb * 512 + 256 + k] = lo;
}

// ============================================================================
// Edge LSTM (hidden 64, K=128, N=256), merged spatial+temporal.
// Temporal h has separate in/out buffers (stream overlap); spatial in-place.
// ============================================================================
#define E_AHI 0
#define E_ALO 17408
#define E_CS  34816
#define E_INC 52224
#define E_BUF 52736
#define E_BUFSZ 20480
#define EDGE_SMEM (52736 + 3 * 20480)
#define SE_BLOCKS (EE / 64)

__global__ __launch_bounds__(256, 2) void edge_mma4_kernel(
    const float* __restrict__ x_s, const float* __restrict__ x_t,
    const float* __restrict__ encw_s, const float* __restrict__ encb_s,
    const float* __restrict__ encw_t, const float* __restrict__ encb_t,
    const __nv_bfloat16* __restrict__ W2t_s, const __nv_bfloat16* __restrict__ W2t_t,
    const float* __restrict__ bias_s, const float* __restrict__ bias_t,
    float* __restrict__ h_s, float* __restrict__ c_s,
    const float* __restrict__ h_t_in, float* __restrict__ h_t_out,
    float* __restrict__ c_t,
    float* __restrict__ agg, const int* __restrict__ inc)
{
    extern __shared__ char sm[];
    const uint32_t sb = smem_u32(sm);
    const int tid = threadIdx.x;
    const int wid = tid >> 5, l = tid & 31;
    const int mw = wid & 1, nw = wid >> 1;
    const int m0 = mw * 32;

    const bool is_se = (blockIdx.x < SE_BLOCKS);
    const int row0 = (is_se ? blockIdx.x : (blockIdx.x - SE_BLOCKS)) * 64;
    const float* x    = is_se ? x_s : x_t;
    const float* encw = is_se ? encw_s : encw_t;
    const float* encb = is_se ? encb_s : encb_t;
    const __nv_bfloat16* W2t = is_se ? W2t_s : W2t_t;
    const float* bias = is_se ? bias_s : bias_t;
    const float* hIn = is_se ? h_s : h_t_in;
    float* hOut = is_se ? h_s : h_t_out;
    float* c = is_se ? c_s : c_t;
    float* aggp = is_se ? agg : nullptr;

    // ---- group 0: B chunk0 + Cs_in (c tile) + inc ----
    #pragma unroll
    for (int it = 0; it < 4; ++it) {
        int idx = tid + it * 256;
        int r = idx >> 2, k8 = idx & 3;
        CP16(sb + E_BUF + r * 80 + k8 * 16, W2t + (size_t)r * 256 + 0 * 32 + k8 * 8);
    }
    #pragma unroll
    for (int it = 0; it < 4; ++it) {
        int idx = tid + it * 256;
        int r = idx >> 4, seg = idx & 15;
        CP16(sb + E_CS + r * 272 + seg * 16, c + (size_t)(row0 + r) * 64 + seg * 4);
    }
    if (is_se && tid < 32)
        CP16(sb + E_INC + tid * 16, inc + 2 * row0 + tid * 4);
    CP_COMMIT();
    // ---- group 1: B chunk1 ----
    #pragma unroll
    for (int it = 0; it < 4; ++it) {
        int idx = tid + it * 256;
        int r = idx >> 2, k8 = idx & 3;
        CP16(sb + E_BUF + E_BUFSZ + r * 80 + k8 * 16, W2t + (size_t)r * 256 + 1 * 32 + k8 * 8);
    }
    CP_COMMIT();

    // ---- stage A (enc cols 0..63, h cols 64..127), split planes ----
    #pragma unroll
    for (int it = 0; it < 8; ++it) {
        int idx = tid + it * 256;
        int r = idx >> 5, j4 = idx & 31;
        int R = row0 + r;
        if (j4 < 16) {
            float x0 = x[R * 2 + 0], x1 = x[R * 2 + 1];
            int j = j4 * 4;
            #pragma unroll
            for (int e = 0; e < 2; ++e) {
                int cc = j + e * 2;
                float v0 = fmaxf(fmaf(x0, __ldg(&encw[cc]),     fmaf(x1, __ldg(&encw[64 + cc]),     __ldg(&encb[cc]))), 0.f);
                float v1 = fmaxf(fmaf(x0, __ldg(&encw[cc + 1]), fmaf(x1, __ldg(&encw[64 + cc + 1]), __ldg(&encb[cc + 1]))), 0.f);
                split2_store(sm + E_AHI, sm + E_ALO, r * 272 + cc * 2, v0, v1);
            }
        } else {
            int j = (j4 - 16) * 4;
            float4 hv = *(const float4*)&hIn[(size_t)R * 64 + j];
            split2_store(sm + E_AHI, sm + E_ALO, r * 272 + (64 + j) * 2, hv.x, hv.y);
            split2_store(sm + E_AHI, sm + E_ALO, r * 272 + (64 + j + 2) * 2, hv.z, hv.w);
        }
    }

    // ---- lane-constant offsets ----
    const int qi = l >> 3, ii = l & 7;
    const uint32_t b_lane = ((qi >= 2 ? 8u : 0u) + (uint32_t)ii) * 80u + (qi & 1) * 16u;
    const uint32_t a_lane = (uint32_t)(l & 15) * 272u + (uint32_t)(l >> 4) * 16u;
    const uint32_t aHiB = sb + E_AHI + m0 * 272 + a_lane;
    const uint32_t aLoB = sb + E_ALO + m0 * 272 + a_lane;
    const uint32_t bWarp = nw * 5120 + b_lane;

    float acc[2][8][4];
    #pragma unroll
    for (int mt = 0; mt < 2; ++mt)
        #pragma unroll
        for (int nt = 0; nt < 8; ++nt)
            #pragma unroll
            for (int e = 0; e < 4; ++e) acc[mt][nt][e] = 0.f;

    // ---- mainloop: 8 k32 chunks (hi 0..3, lo 4..7) ----
    for (int cc = 0; cc < 8; ++cc) {
        if (cc < 7) { CP_WAIT1(); } else { CP_WAIT0(); }
        __syncthreads();

        if (cc + 2 < 8) {
            const int cn2 = cc + 2;
            const uint32_t dstb = sb + E_BUF + (cn2 % 3) * E_BUFSZ;
            #pragma unroll
            for (int it = 0; it < 4; ++it) {
                int idx = tid + it * 256;
                int r = idx >> 2, k8 = idx & 3;
                CP16(dstb + r * 80 + k8 * 16, W2t + (size_t)r * 256 + cn2 * 32 + k8 * 8);
            }
            CP_COMMIT();
        }

        const uint32_t bufB = sb + E_BUF + (cc % 3) * E_BUFSZ + bWarp;
        const bool hiChunk = (cc < 4);
        const uint32_t acol = (uint32_t)(cc & 3) * 64;

        #pragma unroll
        for (int ks2 = 0; ks2 < 2; ++ks2) {
            uint32_t bb[8][2];
            #pragma unroll
            for (int fg = 0; fg < 4; ++fg) {
                uint32_t r0, r1, r2, r3;
                LDSM4(r0, r1, r2, r3, bufB + fg * 1280 + ks2 * 32);
                bb[fg * 2][0] = r0;     bb[fg * 2][1] = r1;
                bb[fg * 2 + 1][0] = r2; bb[fg * 2 + 1][1] = r3;
            }
            #pragma unroll
            for (int ap = 0; ap < 2; ++ap) {
                if (!hiChunk && ap == 1) continue;
                #pragma unroll
                for (int mt = 0; mt < 2; ++mt) {
                    uint32_t a0, a1, a2, a3;
                    LDSM4(a0, a1, a2, a3, (ap ? aLoB : aHiB) + mt * 4352 + acol + ks2 * 32);
                    #pragma unroll
                    for (int nt = 0; nt < 8; ++nt)
                        MMA_BF16(acc[mt][nt], a0, a1, a2, a3, bb[nt][0], bb[nt][1]);
                }
            }
        }
    }

    // ---- epilogue: gates -> staged h/c in reused A region (272B stride) ----
    __syncthreads();

    const int rl_base = m0 + (l >> 2);
    #pragma unroll
    for (int mt = 0; mt < 2; ++mt) {
        #pragma unroll
        for (int rh = 0; rh < 2; ++rh) {
            int rl = rl_base + mt * 16 + rh * 8;
            #pragma unroll
            for (int u = 0; u < 2; ++u) {
                int j0 = nw * 16 + u * 8 + 2 * (l & 3);
                float i0 = acc[mt][u][rh * 2]          + __ldg(&bias[j0]);
                float i1 = acc[mt][u][rh * 2 + 1]      + __ldg(&bias[j0 + 1]);
                float f0 = acc[mt][2 + u][rh * 2]      + __ldg(&bias[64 + j0]);
                float f1 = acc[mt][2 + u][rh * 2 + 1]  + __ldg(&bias[64 + j0 + 1]);
                float g0 = acc[mt][4 + u][rh * 2]      + __ldg(&bias[128 + j0]);
                float g1 = acc[mt][4 + u][rh * 2 + 1]  + __ldg(&bias[128 + j0 + 1]);
                float o0 = acc[mt][6 + u][rh * 2]      + __ldg(&bias[192 + j0]);
                float o1 = acc[mt][6 + u][rh * 2 + 1]  + __ldg(&bias[192 + j0 + 1]);
                float2 cold = *(const float2*)(sm + E_CS + rl * 272 + j0 * 4);
                float c0 = sigf(f0) * cold.x + sigf(i0) * tanh_f(g0);
                float c1 = sigf(f1) * cold.y + sigf(i1) * tanh_f(g1);
                float h0 = sigf(o0) * tanh_f(c0);
                float h1 = sigf(o1) * tanh_f(c1);
                *(float2*)(sm + rl * 272 + j0 * 4)         = make_float2(h0, h1);
                *(float2*)(sm + 17408 + rl * 272 + j0 * 4) = make_float2(c0, c1);
            }
        }
    }
    __syncthreads();

    // ---- cooperative coalesced writeback + vector red scatter ----
    const int* incs = (const int*)(sm + E_INC);
    #pragma unroll
    for (int p = 0; p < 4; ++p) {
        int r = p * 16 + (tid >> 4);
        int j4 = tid & 15;
        int R = row0 + r;
        float4 hv = *(const float4*)(sm + r * 272 + j4 * 16);
        float4 cv = *(const float4*)(sm + 17408 + r * 272 + j4 * 16);
        *(float4*)&hOut[(size_t)R * 64 + j4 * 4] = hv;
        *(float4*)&c[(size_t)R * 64 + j4 * 4] = cv;
        if (aggp) {
            int n0 = incs[2 * r], n1 = incs[2 * r + 1];
            RED4(&aggp[(size_t)n0 * 64 + j4 * 4], hv);
            RED4(&aggp[(size_t)n1 * 64 + j4 * 4], hv);
        }
    }
}

// ============================================================================
// emb kernel: enc/emb + hn snapshot into planes.
// ============================================================================
#define EMB_SMEM (64 * 132 * 4 + 128 * 64 * 4)

__global__ __launch_bounds__(256) void emb_kernel(
    const float* __restrict__ xn,
    const float* __restrict__ nencw, const float* __restrict__ nencb,
    const float* __restrict__ eew,   const float* __restrict__ eeb,
    const float* __restrict__ ht,    const float* __restrict__ agg,
    const float* __restrict__ hn,
    __nv_bfloat16* __restrict__ xeh, __nv_bfloat16* __restrict__ xel)
{
    extern __shared__ float smf[];
    float* Asf  = smf;
    float* eewS = smf + 64 * 132;

    const int tid = threadIdx.x;
    const int row0 = blockIdx.x * 64;

    #pragma unroll
    for (int it = 0; it < 16; ++it) {
        int idx = tid + it * 256;
        int r = idx >> 6, j = idx & 63;
        int R = row0 + r;
        Asf[r * 132 + j]      = ht[(size_t)R * 64 + j];
        Asf[r * 132 + 64 + j] = agg[(size_t)R * 64 + j];
    }
    #pragma unroll
    for (int it = 0; it < 8; ++it) {
        int f4 = tid + it * 256;
        *(float4*)&eewS[f4 * 4] = *(const float4*)&eew[f4 * 4];
    }

    #pragma unroll
    for (int it = 0; it < 16; ++it) {
        int idx = tid + it * 256;
        int r = idx >> 6, jp = idx & 63;
        int R = row0 + r;
        float2 hv = *(const float2*)&hn[(size_t)R * 128 + jp * 2];
        split2_store((char*)(xeh + (size_t)R * 256), (char*)(xel + (size_t)R * 256),
                     (128 + jp * 2) * 2, hv.x, hv.y);
    }
    __syncthreads();

    const int r = tid >> 2, jq = tid & 3;
    const int R = row0 + r;

    {
        float xv = xn[R];
        #pragma unroll
        for (int u = 0; u < 8; ++u) {
            int cc = jq * 16 + u * 2;
            float v0 = fmaxf(fmaf(xv, __ldg(&nencw[cc]),     __ldg(&nencb[cc])), 0.f);
            float v1 = fmaxf(fmaf(xv, __ldg(&nencw[cc + 1]), __ldg(&nencb[cc + 1])), 0.f);
            split2_store((char*)(xeh + (size_t)R * 256), (char*)(xel + (size_t)R * 256),
                         cc * 2, v0, v1);
        }
    }

    {
        float accv[16];
        #pragma unroll
        for (int u = 0; u < 16; ++u) accv[u] = __ldg(&eeb[jq * 16 + u]);
        #pragma unroll 4
        for (int k = 0; k < 128; ++k) {
            float a = Asf[r * 132 + k];
            #pragma unroll
            for (int g = 0; g < 4; ++g) {
                float4 w4 = *(const float4*)&eewS[k * 64 + jq * 16 + g * 4];
                accv[g*4+0] = fmaf(a, w4.x, accv[g*4+0]);
                accv[g*4+1] = fmaf(a, w4.y, accv[g*4+1]);
                accv[g*4+2] = fmaf(a, w4.z, accv[g*4+2]);
                accv[g*4+3] = fmaf(a, w4.w, accv[g*4+3]);
            }
        }
        #pragma unroll
        for (int u = 0; u < 8; ++u) {
            float v0 = fmaxf(accv[u * 2], 0.f);
            float v1 = fmaxf(accv[u * 2 + 1], 0.f);
            int cc = 64 + jq * 16 + u * 2;
            split2_store((char*)(xeh + (size_t)R * 256), (char*)(xel + (size_t)R * 256),
                         cc * 2, v0, v1);
        }
    }
}

// ============================================================================
// Node LSTM GEMM (hidden 128, K=256). Grid (NN/64, 2).
// ============================================================================
#define N_AHI 0
#define N_ALO 33792
#define N_BUF 67584
#define N_BUFSZ 12288
#define NODE_SMEM (67584 + 3 * 12288)

__global__ __launch_bounds__(256, 2) void node_mma4_kernel(
    const __nv_bfloat16* __restrict__ xeh, const __nv_bfloat16* __restrict__ xel,
    const __nv_bfloat16* __restrict__ W2t,
    const float* __restrict__ bias,
    const float* __restrict__ outw,  const float* __restrict__ outb,
    float* __restrict__ hn, float* __restrict__ cn,
    float* __restrict__ out)
{
    extern __shared__ char sm[];
    const uint32_t sb = smem_u32(sm);
    const int tid = threadIdx.x;
    const int wid = tid >> 5, l = tid & 31;
    const int mw = wid & 1, nw = wid >> 1;
    const int m0 = mw * 32;
    const int row0 = blockIdx.x * 64;
    const int nh = blockIdx.y;
    const __nv_bfloat16* Wb = W2t + (size_t)(nh * 256) * 512;

    // ---- group 0: stage A ----
    #pragma unroll
    for (int it = 0; it < 16; ++it) {
        int idx = tid + it * 256;
        int plane = idx >> 11;
        int i2 = idx & 2047;
        int r = i2 >> 5, k8 = i2 & 31;
        const __nv_bfloat16* src = (plane ? xel : xeh) + (size_t)(row0 + r) * 256 + k8 * 8;
        CP16(sb + (plane ? N_ALO : N_AHI) + r * 528 + k8 * 16, src);
    }
    CP_COMMIT();

    // ---- groups 1,2: preload B chunks 0,1 ----
    #pragma unroll
    for (int it = 0; it < 2; ++it) {
        int idx = tid + it * 256;
        int r = idx >> 1, k8 = idx & 1;
        CP16(sb + N_BUF + r * 48 + k8 * 16, Wb + (size_t)r * 512 + 0 * 16 + k8 * 8);
    }
    CP_COMMIT();
    #pragma unroll
    for (int it = 0; it < 2; ++it) {
        int idx = tid + it * 256;
        int r = idx >> 1, k8 = idx & 1;
        CP16(sb + N_BUF + N_BUFSZ + r * 48 + k8 * 16, Wb + (size_t)r * 512 + 1 * 16 + k8 * 8);
    }
    CP_COMMIT();

    // ---- cold (cn) register prefetch ----
    float2 cold[2][2][2];
    #pragma unroll
    for (int mt = 0; mt < 2; ++mt)
        #pragma unroll
        for (int rh = 0; rh < 2; ++rh)
            #pragma unroll
            for (int u = 0; u < 2; ++u) {
                int R = row0 + m0 + (l >> 2) + mt * 16 + rh * 8;
                int j0 = nh * 64 + nw * 16 + u * 8 + 2 * (l & 3);
                cold[mt][rh][u] = __ldg((const float2*)&cn[(size_t)R * 128 + j0]);
            }

    const int qi = l >> 3, ii = l & 7;
    const uint32_t b_lane = ((qi >= 2 ? 8u : 0u) + (uint32_t)ii) * 48u + (qi & 1) * 16u;
    const uint32_t a_lane = (uint32_t)(l & 15) * 528u + (uint32_t)(l >> 4) * 16u;
    const uint32_t aHiB = sb + N_AHI + m0 * 528 + a_lane;
    const uint32_t aLoB = sb + N_ALO + m0 * 528 + a_lane;
    const uint32_t bWarp = nw * 3072 + b_lane;

    float acc[2][8][4];
    #pragma unroll
    for (int mt = 0; mt < 2; ++mt)
        #pragma unroll
        for (int nt = 0; nt < 8; ++nt)
            #pragma unroll
            for (int e = 0; e < 4; ++e) acc[mt][nt][e] = 0.f;

    for (int cc = 0; cc < 32; ++cc) {
        if (cc < 31) { CP_WAIT1(); } else { CP_WAIT0(); }
        __syncthreads();

        if (cc + 2 < 32) {
            const int cn2 = cc + 2;
            const uint32_t dstb = sb + N_BUF + (cn2 % 3) * N_BUFSZ;
            #pragma unroll
            for (int it = 0; it < 2; ++it) {
                int idx = tid + it * 256;
                int r = idx >> 1, k8 = idx & 1;
                CP16(dstb + r * 48 + k8 * 16, Wb + (size_t)r * 512 + cn2 * 16 + k8 * 8);
            }
            CP_COMMIT();
        }

        const uint32_t bufB = sb + N_BUF + (cc % 3) * N_BUFSZ + bWarp;
        const bool hiChunk = (cc < 16);
        const uint32_t acol = (uint32_t)(cc & 15) * 32;

        uint32_t bb[8][2];
        #pragma unroll
        for (int fg = 0; fg < 4; ++fg) {
            uint32_t r0, r1, r2, r3;
            LDSM4(r0, r1, r2, r3, bufB + fg * 768);
            bb[fg * 2][0] = r0;     bb[fg * 2][1] = r1;
            bb[fg * 2 + 1][0] = r2; bb[fg * 2 + 1][1] = r3;
        }
        #pragma unroll
        for (int ap = 0; ap < 2; ++ap) {
            if (!hiChunk && ap == 1) continue;
            #pragma unroll
            for (int mt = 0; mt < 2; ++mt) {
                uint32_t a0, a1, a2, a3;
                LDSM4(a0, a1, a2, a3, (ap ? aLoB : aHiB) + mt * 8448 + acol);
                #pragma unroll
                for (int nt = 0; nt < 8; ++nt)
                    MMA_BF16(acc[mt][nt], a0, a1, a2, a3, bb[nt][0], bb[nt][1]);
            }
        }
    }

    // ---- epilogue: gates -> staged h/c (272B stride) ----
    __syncthreads();

    const float ob = (nh == 0 && nw == 0) ? __ldg(outb) : 0.f;
    const int rl_base = m0 + (l >> 2);
    #pragma unroll
    for (int mt = 0; mt < 2; ++mt) {
        #pragma unroll
        for (int rh = 0; rh < 2; ++rh) {
            int rl = rl_base + mt * 16 + rh * 8;
            int R = row0 + rl;
            float po = 0.f;
            #pragma unroll
            for (int u = 0; u < 2; ++u) {
                int j0 = nh * 64 + nw * 16 + u * 8 + 2 * (l & 3);
                int jl = j0 - nh * 64;
                float i0 = acc[mt][u][rh * 2]          + __ldg(&bias[j0]);
                float i1 = acc[mt][u][rh * 2 + 1]      + __ldg(&bias[j0 + 1]);
                float f0 = acc[mt][2 + u][rh * 2]      + __ldg(&bias[128 + j0]);
                float f1 = acc[mt][2 + u][rh * 2 + 1]  + __ldg(&bias[128 + j0 + 1]);
                float g0 = acc[mt][4 + u][rh * 2]      + __ldg(&bias[256 + j0]);
                float g1 = acc[mt][4 + u][rh * 2 + 1]  + __ldg(&bias[256 + j0 + 1]);
                float o0 = acc[mt][6 + u][rh * 2]      + __ldg(&bias[384 + j0]);
                float o1 = acc[mt][6 + u][rh * 2 + 1]  + __ldg(&bias[384 + j0 + 1]);
                float2 cv = cold[mt][rh][u];
                float c0 = sigf(f0) * cv.x + sigf(i0) * tanh_f(g0);
                float c1 = sigf(f1) * cv.y + sigf(i1) * tanh_f(g1);
                float h0 = sigf(o0) * tanh_f(c0);
                float h1 = sigf(o1) * tanh_f(c1);
                *(float2*)(sm + rl * 272 + jl * 4)         = make_float2(h0, h1);
                *(float2*)(sm + 17408 + rl * 272 + jl * 4) = make_float2(c0, c1);
                po = fmaf(h0, __ldg(&outw[j0]), po);
                po = fmaf(h1, __ldg(&outw[j0 + 1]), po);
            }
            po += __shfl_xor_sync(0xffffffffu, po, 1);
            po += __shfl_xor_sync(0xffffffffu, po, 2);
            if ((l & 3) == 0) atomicAdd(&out[R], po + ob);
        }
    }
    __syncthreads();

    #pragma unroll
    for (int p = 0; p < 4; ++p) {
        int r = p * 16 + (tid >> 4);
        int j4 = tid & 15;
        int R = row0 + r;
        float4 hv = *(const float4*)(sm + r * 272 + j4 * 16);
        float4 cv = *(const float4*)(sm + 17408 + r * 272 + j4 * 16);
        *(float4*)&hn[(size_t)R * 128 + nh * 64 + j4 * 4] = hv;
        *(float4*)&cn[(size_t)R * 128 + nh * 64 + j4 * 4] = cv;
    }
}

// ============================================================================
extern "C" void kernel_launch(void* const* d_in, const int* in_sizes, int n_in,
                              void* d_out, int out_size) {
    const float* data_nodes = (const float*)d_in[0];
    const float* data_te    = (const float*)d_in[1];
    const float* data_se    = (const float*)d_in[2];
    const float* h_n0 = (const float*)d_in[3];
    const float* c_n0 = (const float*)d_in[4];
    const float* h_t0 = (const float*)d_in[5];
    const float* c_t0 = (const float*)d_in[6];
    const float* h_s0 = (const float*)d_in[7];
    const float* c_s0 = (const float*)d_in[8];
    const int*   inc  = (const int*)d_in[9];
    const float* t_enc_w = (const float*)d_in[10];
    const float* t_enc_b = (const float*)d_in[11];
    const float* t_Wih   = (const float*)d_in[12];
    const float* t_Whh   = (const float*)d_in[13];
    const float* t_b     = (const float*)d_in[14];
    const float* s_enc_w = (const float*)d_in[15];
    const float* s_enc_b = (const float*)d_in[16];
    const float* s_Wih   = (const float*)d_in[17];
    const float* s_Whh   = (const float*)d_in[18];
    const float* s_b     = (const float*)d_in[19];
    const float* n_enc_w = (const float*)d_in[20];
    const float* n_enc_b = (const float*)d_in[21];
    const float* ee_w    = (const float*)d_in[22];
    const float* ee_b    = (const float*)d_in[23];
    const float* n_Wih   = (const float*)d_in[24];
    const float* n_Whh   = (const float*)d_in[25];
    const float* n_b     = (const float*)d_in[26];
    const float* out_w   = (const float*)d_in[27];
    const float* out_b   = (const float*)d_in[28];
    float* out = (float*)d_out;

    float *hs, *cs, *ht3, *ct, *hn, *cn, *agg2;
    __nv_bfloat16 *w2t_s, *w2t_t, *w2t_n, *xeh, *xel;
    cudaGetSymbolAddress((void**)&hs,  g_hs);
    cudaGetSymbolAddress((void**)&cs,  g_cs);
    cudaGetSymbolAddress((void**)&ht3, g_ht3);
    cudaGetSymbolAddress((void**)&ct,  g_ct);
    cudaGetSymbolAddress((void**)&hn,  g_hn);
    cudaGetSymbolAddress((void**)&cn,  g_cn);
    cudaGetSymbolAddress((void**)&agg2, g_agg2);
    cudaGetSymbolAddress((void**)&w2t_s, g_w2t_s);
    cudaGetSymbolAddress((void**)&w2t_t, g_w2t_t);
    cudaGetSymbolAddress((void**)&w2t_n, g_w2t_n);
    cudaGetSymbolAddress((void**)&xeh, g_xeh);
    cudaGetSymbolAddress((void**)&xel, g_xel);

    // one-time stream/event setup (resource-only; captured work is identical
    // on every call)
    static bool s_init = false;
    static cudaStream_t s1, s2;
    static cudaEvent_t evRoot, evJ1, evJ2;
    static cudaEvent_t evEdge[SSTEPS], evEmb[SSTEPS];
    if (!s_init) {
        s_init = true;
        cudaStreamCreateWithFlags(&s1, cudaStreamNonBlocking);
        cudaStreamCreateWithFlags(&s2, cudaStreamNonBlocking);
        cudaEventCreateWithFlags(&evRoot, cudaEventDisableTiming);
        cudaEventCreateWithFlags(&evJ1, cudaEventDisableTiming);
        cudaEventCreateWithFlags(&evJ2, cudaEventDisableTiming);
        for (int t = 0; t < SSTEPS; ++t) {
            cudaEventCreateWithFlags(&evEdge[t], cudaEventDisableTiming);
            cudaEventCreateWithFlags(&evEmb[t], cudaEventDisableTiming);
        }
        cudaFuncSetAttribute(edge_mma4_kernel, cudaFuncAttributeMaxDynamicSharedMemorySize, EDGE_SMEM);
        cudaFuncSetAttribute(node_mma4_kernel, cudaFuncAttributeMaxDynamicSharedMemorySize, NODE_SMEM);
        cudaFuncSetAttribute(emb_kernel,       cudaFuncAttributeMaxDynamicSharedMemorySize, EMB_SMEM);
    }

    // ---- prologue on the capture (default) stream ----
    cudaMemcpyAsync(hs, h_s0, (size_t)EE * 64  * 4, cudaMemcpyDeviceToDevice);
    cudaMemcpyAsync(cs, c_s0, (size_t)EE * 64  * 4, cudaMemcpyDeviceToDevice);
    cudaMemcpyAsync(ht3, h_t0, (size_t)NN * 64 * 4, cudaMemcpyDeviceToDevice);  // buffer 0
    cudaMemcpyAsync(ct, c_t0, (size_t)NN * 64  * 4, cudaMemcpyDeviceToDevice);
    cudaMemcpyAsync(hn, h_n0, (size_t)NN * 128 * 4, cudaMemcpyDeviceToDevice);
    cudaMemcpyAsync(cn, c_n0, (size_t)NN * 128 * 4, cudaMemcpyDeviceToDevice);
    cudaMemsetAsync(out, 0, (size_t)SSTEPS * NN * 4);

    prep_edge_w<<<128, 256>>>(s_Wih, s_Whh, w2t_s);
    prep_edge_w<<<128, 256>>>(t_Wih, t_Whh, w2t_t);
    prep_node_w<<<512, 256>>>(n_Wih, n_Whh, w2t_n);

    // ---- fork ----
    cudaEventRecord(evRoot, 0);
    cudaStreamWaitEvent(s1, evRoot, 0);
    cudaStreamWaitEvent(s2, evRoot, 0);

    const int edge_grid = SE_BLOCKS + NN / 64;   // 2048 + 512
    const size_t HTB = (size_t)NN * 64;          // one ht buffer, floats

    for (int t = 0; t < SSTEPS; ++t) {
        float* aggT  = agg2 + (size_t)(t & 1) * HTB;
        float* htIn  = ht3 + (size_t)(t % 3) * HTB;
        float* htOut = ht3 + (size_t)((t + 1) % 3) * HTB;

        // stream 1: edges (sequential chain)
        if (t >= 2) cudaStreamWaitEvent(s1, evEmb[t - 2], 0);
        cudaMemsetAsync(aggT, 0, HTB * 4, s1);
        edge_mma4_kernel<<<edge_grid, 256, EDGE_SMEM, s1>>>(
            data_se + (size_t)t * EE * 2, data_te + (size_t)t * NN * 2,
            s_enc_w, s_enc_b, t_enc_w, t_enc_b,
            w2t_s, w2t_t, s_b, t_b,
            hs, cs, htIn, htOut, ct, aggT, inc);
        cudaEventRecord(evEdge[t], s1);

        // stream 2: emb + node for step t
        cudaStreamWaitEvent(s2, evEdge[t], 0);
        emb_kernel<<<NN / 64, 256, EMB_SMEM, s2>>>(
            data_nodes + (size_t)t * NN,
            n_enc_w, n_enc_b, ee_w, ee_b,
            htOut, aggT, hn, xeh, xel);
        cudaEventRecord(evEmb[t], s2);
        node_mma4_kernel<<<dim3(NN / 64, 2), 256, NODE_SMEM, s2>>>(
            xeh, xel, w2t_n, n_b, out_w, out_b,
            hn, cn, out + (size_t)t * NN);
    }

    // ---- join back to the capture stream ----
    cudaEventRecord(evJ1, s1);
    cudaEventRecord(evJ2, s2);
    cudaStreamWaitEvent(0, evJ1, 0);
    cudaStreamWaitEvent(0, evJ2, 0);
}